// round 12
// baseline (speedup 1.0000x reference)
#include <cuda_runtime.h>
#include <cuda_bf16.h>
#include <cstdint>

// ============================================================================
// LocalBranch round 12: R11 (542us) + cross-GEMM bulk prefetch (next GEMM's
// first two chunks are issued during the current GEMM's tail and fly during
// the epilogue -> no exposed first-chunk latency) + one epilogue sync removed.
//  Kernel A (mlp): 2048 CTAs x 256 thr, 64 nodes each, bf16x3 mma.sync,
//    ldsm-ready 128B-tile-packed k16 chunks, 2-slot cp.async.bulk ring.
//  Kernel B (pool): 1024 CTAs x 256 thr; Gram via bf16x3 mma, softmax, pool.
// ============================================================================

namespace lb {

using u32 = uint32_t;

constexpr int NODES = 128, IND = 64, HID = 256, OUTD = 128, NBLK = 3, NG = 1024;

// ---- kernel A smem ----
constexpr int TPA   = 256;
constexpr int XA_RS = 528;               // x-plane row stride (bytes)
constexpr int XA_PL = 64 * XA_RS;        // 33792 per plane (64 rows)
constexpr int A_RING = 2 * XA_PL;        // 67584
constexpr int A_SLOTB = 16384;           // max chunk bytes (N=256)
constexpr int A_PART = A_RING + 2 * A_SLOTB;   // 100352: float2[64*4]
constexpr int A_MB   = A_PART + 2048;    // 102400: 2 mbarriers
constexpr int SMEM_A = A_MB + 48;        // 102448 (x2 = 204896 <= 228KB)

// ---- kernel B smem ----
constexpr int TPBB  = 256;
constexpr int ZB_RS = 272;               // z-plane row stride (bytes)
constexpr int ZB_PL = 128 * ZB_RS;       // 34816 per plane
constexpr int B_SQ   = 2 * ZB_PL;        // float[128]
constexpr int B_PART = B_SQ + 512;       // float[256]
constexpr int B_SSM  = B_PART + 1024;    // float[128]
constexpr int B_WSM  = B_SSM + 512;      // float[128]
constexpr int B_VP   = B_WSM + 512;      // float[256]
constexpr int SMEM_B = B_VP + 1024;      // 73216

// ---- weight image: k16 chunks of ldsm-ready 128B tiles (see prep) ----
constexpr long IMG_STEM   = 0;                    // 4 chunks x 16384
constexpr long IMG_BLK    = 65536;                // 3 x 16 x 16384
constexpr long IMG_BLKSTR = 262144;
constexpr long IMG_HEAD   = 851968;               // 16 x 8192
__device__ __align__(128) unsigned char g_wimg[983040];
__device__ float g_z[(size_t)NG * NODES * OUTD];  // 64 MB scratch

// ---------------- PTX helpers ----------------
__device__ __forceinline__ u32 s2u(const void* p) {
    u32 a;
    asm("{ .reg .u64 t; cvta.to.shared.u64 t, %1; cvt.u32.u64 %0, t; }"
        : "=r"(a) : "l"(p));
    return a;
}
__device__ __forceinline__ void ldsm4(u32* r, u32 addr) {
    asm volatile("ldmatrix.sync.aligned.m8n8.x4.shared.b16 {%0,%1,%2,%3}, [%4];"
                 : "=r"(r[0]), "=r"(r[1]), "=r"(r[2]), "=r"(r[3]) : "r"(addr));
}
__device__ __forceinline__ void mma16816(float* c, const u32* a, u32 b0, u32 b1) {
    asm volatile(
        "mma.sync.aligned.m16n8k16.row.col.f32.bf16.bf16.f32 "
        "{%0,%1,%2,%3}, {%4,%5,%6,%7}, {%8,%9}, {%0,%1,%2,%3};"
        : "+f"(c[0]), "+f"(c[1]), "+f"(c[2]), "+f"(c[3])
        : "r"(a[0]), "r"(a[1]), "r"(a[2]), "r"(a[3]), "r"(b0), "r"(b1));
}
__device__ __forceinline__ void mbar_init(u32 mb, u32 c) {
    asm volatile("mbarrier.init.shared.b64 [%0], %1;" :: "r"(mb), "r"(c)
                 : "memory");
}
__device__ __forceinline__ void mbar_expect_tx(u32 mb, u32 tx) {
    asm volatile("mbarrier.arrive.expect_tx.shared.b64 _, [%0], %1;"
                 :: "r"(mb), "r"(tx) : "memory");
}
__device__ __forceinline__ void bulk_g2s(u32 dst, const void* src, u32 bytes,
                                         u32 mb) {
    asm volatile(
        "cp.async.bulk.shared::cta.global.mbarrier::complete_tx::bytes "
        "[%0], [%1], %2, [%3];"
        :: "r"(dst), "l"(src), "r"(bytes), "r"(mb) : "memory");
}
__device__ __forceinline__ void mbar_wait(u32 mb, u32 parity) {
    asm volatile(
        "{\n\t.reg .pred P;\n\t"
        "W%=:\n\t"
        "mbarrier.try_wait.parity.acquire.cta.shared::cta.b64 P, [%0], %1, 0x989680;\n\t"
        "@!P bra W%=;\n\t}"
        :: "r"(mb), "r"(parity) : "memory");
}

// ---------------- bf16 pack helpers ----------------
__device__ __forceinline__ u32 packbf(float x0, float x1) {
    unsigned short a = __bfloat16_as_ushort(__float2bfloat16(x0));
    unsigned short b = __bfloat16_as_ushort(__float2bfloat16(x1));
    return (u32)a | ((u32)b << 16);
}
__device__ __forceinline__ float bflo(u32 p) {
    return __bfloat162float(__ushort_as_bfloat16((unsigned short)(p & 0xffff)));
}
__device__ __forceinline__ float bfhi(u32 p) {
    return __bfloat162float(__ushort_as_bfloat16((unsigned short)(p >> 16)));
}
__device__ __forceinline__ float bf2f(unsigned short v) {
    return __bfloat162float(__ushort_as_bfloat16(v));
}
__device__ __forceinline__ float warpsum(float v) {
#pragma unroll
    for (int o = 16; o; o >>= 1) v += __shfl_xor_sync(0xffffffffu, v, o);
    return v;
}

// ---------------- prep: weights -> split, tile-packed k16-chunk image ------
__global__ void prep(const float* __restrict__ Wi, const float* __restrict__ Wb,
                     const float* __restrict__ Wo) {
    int idx = blockIdx.x * 256 + threadIdx.x;        // 245760 total
    const float* W; int k, n, N; long base;
    if (idx < 16384) {
        W = Wi; N = 256; k = idx >> 8; n = idx & 255; base = IMG_STEM;
    } else if (idx < 212992) {
        int e = idx - 16384; int b = e >> 16; e &= 65535;
        W = Wb + (size_t)b * 65536; N = 256; k = e >> 8; n = e & 255;
        base = IMG_BLK + (long)b * IMG_BLKSTR;
    } else {
        int e = idx - 212992;
        W = Wo; N = 128; k = e >> 7; n = e & 127; base = IMG_HEAD;
    }
    float w = W[(size_t)k * N + n];
    __nv_bfloat16 h = __float2bfloat16(w);
    __nv_bfloat16 l = __float2bfloat16(w - __bfloat162float(h));
    int kk = k & 15;
    long off = base + (long)(k >> 4) * ((long)N * 64)
             + (long)(n >> 4) * 512
             + (long)((((n >> 3) & 1) * 2 + (kk >> 3)) * 128)
             + (n & 7) * 16 + (kk & 7) * 2;
    *(__nv_bfloat16*)(g_wimg + off) = h;
    *(__nv_bfloat16*)(g_wimg + off + (long)N * 32) = l;
}

// ---------------- kernel A staged GEMM (bulk ring, cross-GEMM prefetch) ----
template<int N>   // 256 or 128
__device__ __forceinline__ void gemmA(
    u32 smb, const unsigned char* img, int nchunk,
    const unsigned char* next_img, u32 next_cb, bool first,
    float (&acc)[2][8][4], int tid, int lane, int m0, int nq,
    int a_row, int a_kh, int (&ph)[2])
{
    constexpr int NH = N / 128;            // n16-pair groups per warp (2|1)
    constexpr u32 CB = (u32)N * 64;        // chunk bytes (2 planes)
    const int n16b = nq * (N / 64);        // first n16 index for this warp

    const u32 axh = smb + (u32)(m0 + a_row) * XA_RS + a_kh * 16;
    const u32 axl = axh + XA_PL;
    const u32 mb0 = smb + A_MB;

#pragma unroll
    for (int mt = 0; mt < 2; ++mt)
#pragma unroll
        for (int nt = 0; nt < 8; ++nt)
#pragma unroll
            for (int e = 0; e < 4; ++e) acc[mt][nt][e] = 0.f;

    // entry sync: epilogue plane writes visible; for the first GEMM also
    // covers slot availability + mbar init.
    __syncthreads();
    if (first && tid == 0) {
        mbar_expect_tx(mb0, CB);
        bulk_g2s(smb + A_RING, img, CB, mb0);
        mbar_expect_tx(mb0 + 8, CB);
        bulk_g2s(smb + A_RING + A_SLOTB, img + CB, CB, mb0 + 8);
    }

    for (int ch = 0; ch < nchunk; ++ch) {
        const int s = ch & 1;
        mbar_wait(mb0 + 8 * s, (u32)ph[s]);
        ph[s] ^= 1;
        const u32 slot = smb + A_RING + (u32)s * A_SLOTB;
        const u32 kb = (u32)ch * 32;       // 16 k-values = 32 B in x planes

        u32 ah0[4], ah1[4], al0[4], al1[4];
        ldsm4(ah0, axh + kb);
        ldsm4(ah1, axh + 16 * XA_RS + kb);
        ldsm4(al0, axl + kb);
        ldsm4(al1, axl + 16 * XA_RS + kb);
#pragma unroll
        for (int hf = 0; hf < NH; ++hf) {
            u32 bh[2][4], bl[2][4];
#pragma unroll
            for (int p = 0; p < 2; ++p) {
                const u32 wa = slot + (u32)(n16b + hf * 2 + p) * 512
                             + (u32)lane * 16;
                ldsm4(bh[p], wa);
                ldsm4(bl[p], wa + (u32)N * 32);
            }
            // term 1: Ahi * Bhi
#pragma unroll
            for (int p = 0; p < 2; ++p)
#pragma unroll
                for (int h = 0; h < 2; ++h) {
                    int nt = (hf * 2 + p) * 2 + h;
                    mma16816(acc[0][nt], ah0, bh[p][2*h], bh[p][2*h+1]);
                    mma16816(acc[1][nt], ah1, bh[p][2*h], bh[p][2*h+1]);
                }
            // term 2: Alo * Bhi
#pragma unroll
            for (int p = 0; p < 2; ++p)
#pragma unroll
                for (int h = 0; h < 2; ++h) {
                    int nt = (hf * 2 + p) * 2 + h;
                    mma16816(acc[0][nt], al0, bh[p][2*h], bh[p][2*h+1]);
                    mma16816(acc[1][nt], al1, bh[p][2*h], bh[p][2*h+1]);
                }
            // term 3: Ahi * Blo
#pragma unroll
            for (int p = 0; p < 2; ++p)
#pragma unroll
                for (int h = 0; h < 2; ++h) {
                    int nt = (hf * 2 + p) * 2 + h;
                    mma16816(acc[0][nt], ah0, bl[p][2*h], bl[p][2*h+1]);
                    mma16816(acc[1][nt], ah1, bl[p][2*h], bl[p][2*h+1]);
                }
        }
        // refill slot s with chunk ch+2 -- of this GEMM, or the next GEMM's
        // leading chunks (so they fly during the epilogue).
        const int fi = ch + 2;
        const bool have_next = (next_img != nullptr);
        if (fi < nchunk || (have_next && fi < nchunk + 2)) {
            __syncthreads();   // all warps done reading slot s
            if (tid == 0) {
                if (fi < nchunk) {
                    mbar_expect_tx(mb0 + 8 * s, CB);
                    bulk_g2s(slot, img + (size_t)fi * CB, CB, mb0 + 8 * s);
                } else {
                    mbar_expect_tx(mb0 + 8 * s, next_cb);
                    bulk_g2s(slot, next_img + (size_t)(fi - nchunk) * next_cb,
                             next_cb, mb0 + 8 * s);
                }
            }
        }
    }
}

// ---------------- kernel A: MLP over 64 nodes ----------------
__global__ void __launch_bounds__(TPA, 2)
mlp(const float* __restrict__ H,
    const float* __restrict__ b_in, const float* __restrict__ g_in,
    const float* __restrict__ be_in,
    const float* __restrict__ bb, const float* __restrict__ gb,
    const float* __restrict__ betab,
    const float* __restrict__ b_out, const float* __restrict__ g_out,
    const float* __restrict__ be_out)
{
    extern __shared__ __align__(128) unsigned char smc[];
    const u32 smb = s2u(smc);
    const int tid = threadIdx.x, lane = tid & 31, w = tid >> 5;
    const int qr = lane >> 2, qc = lane & 3;
    const int m0 = (w & 1) * 32, nq = w >> 1;
    const int grp = lane >> 3, ri = lane & 7;
    const int a_row = (grp & 1) * 8 + ri, a_kh = grp >> 1;
    const int g = blockIdx.x >> 1, mh = blockIdx.x & 1;

    float2* part = (float2*)(smc + A_PART);
    int ph[2] = {0, 0};

    if (tid == 0) {
        mbar_init(smb + A_MB, 1);
        mbar_init(smb + A_MB + 8, 1);
    }

    // ---- load H (64 rows, node base mh*64) -> hi/lo planes ----
    {
        const int row = tid >> 2, c4 = tid & 3;
        const float4* hs = (const float4*)(H + (size_t)g * NODES * IND
                                           + (size_t)(mh * 64 + row) * IND
                                           + c4 * 16);
        const u32 off = (u32)row * XA_RS + (u32)c4 * 32;
#pragma unroll
        for (int q = 0; q < 4; ++q) {
            float4 v = hs[q];
            u32 h0 = packbf(v.x, v.y), h1 = packbf(v.z, v.w);
            u32 l0 = packbf(v.x - bflo(h0), v.y - bfhi(h0));
            u32 l1 = packbf(v.z - bflo(h1), v.w - bfhi(h1));
            *(u32*)(smc + off + q * 8)             = h0;
            *(u32*)(smc + off + q * 8 + 4)         = h1;
            *(u32*)(smc + XA_PL + off + q * 8)     = l0;
            *(u32*)(smc + XA_PL + off + q * 8 + 4) = l1;
        }
    }

    float acc[2][8][4];

    // ---- LN(+relu,+residual) epilogue N=256, rewrites x planes ----
    auto ep256 = [&](const float* bias, const float* gam, const float* bet,
                     bool res) {
        const int n0 = nq * 64;
        float s1[4] = {0.f, 0.f, 0.f, 0.f}, s2[4] = {0.f, 0.f, 0.f, 0.f};
#pragma unroll
        for (int nt = 0; nt < 8; ++nt) {
            float2 bp = *(const float2*)&bias[n0 + nt * 8 + qc * 2];
#pragma unroll
            for (int mt = 0; mt < 2; ++mt) {
                float* c = acc[mt][nt];
                c[0] += bp.x; c[1] += bp.y; c[2] += bp.x; c[3] += bp.y;
                s1[mt*2]   += c[0] + c[1];
                s2[mt*2]    = fmaf(c[0], c[0], fmaf(c[1], c[1], s2[mt*2]));
                s1[mt*2+1] += c[2] + c[3];
                s2[mt*2+1]  = fmaf(c[2], c[2], fmaf(c[3], c[3], s2[mt*2+1]));
            }
        }
#pragma unroll
        for (int r = 0; r < 4; ++r) {
            s1[r] += __shfl_xor_sync(0xffffffffu, s1[r], 1);
            s1[r] += __shfl_xor_sync(0xffffffffu, s1[r], 2);
            s2[r] += __shfl_xor_sync(0xffffffffu, s2[r], 1);
            s2[r] += __shfl_xor_sync(0xffffffffu, s2[r], 2);
        }
        __syncthreads();   // guard: planes/part still read by last-chunk mmas
        if (qc == 0) {
#pragma unroll
            for (int r = 0; r < 4; ++r) {
                int row = m0 + (r >> 1) * 16 + (r & 1) * 8 + qr;
                part[row * 4 + nq] = make_float2(s1[r], s2[r]);
            }
        }
        __syncthreads();
        float mu[4], rs[4];
#pragma unroll
        for (int r = 0; r < 4; ++r) {
            int row = m0 + (r >> 1) * 16 + (r & 1) * 8 + qr;
            float4 p0 = *(float4*)&part[row * 4];
            float4 p1 = *(float4*)&part[row * 4 + 2];
            float S1 = p0.x + p0.z + p1.x + p1.z;
            float S2 = p0.y + p0.w + p1.y + p1.w;
            float m_ = S1 * (1.f / 256.f);
            mu[r] = m_;
            rs[r] = rsqrtf(fmaf(-m_, m_, S2 * (1.f / 256.f)) + 1e-5f);
        }
        // (no sync: plane (row,col) below is read+written by the same thread;
        //  next gemmA's entry sync publishes before any cross-thread ldsm)
#pragma unroll
        for (int nt = 0; nt < 8; ++nt) {
            int col = n0 + nt * 8 + qc * 2;
            float2 gg = *(const float2*)&gam[col];
            float2 ee = *(const float2*)&bet[col];
#pragma unroll
            for (int mt = 0; mt < 2; ++mt)
#pragma unroll
                for (int h = 0; h < 2; ++h) {
                    int r4 = mt * 2 + h;
                    int row = m0 + mt * 16 + h * 8 + qr;
                    float v0 = acc[mt][nt][2 * h], v1 = acc[mt][nt][2 * h + 1];
                    float y0 = fmaxf(fmaf((v0 - mu[r4]) * rs[r4], gg.x, ee.x), 0.f);
                    float y1 = fmaxf(fmaf((v1 - mu[r4]) * rs[r4], gg.y, ee.y), 0.f);
                    u32 off = (u32)row * XA_RS + (u32)col * 2;
                    if (res) {
                        u32 oh = *(u32*)(smc + off);
                        u32 ol = *(u32*)(smc + XA_PL + off);
                        y0 += bflo(oh) + bflo(ol);
                        y1 += bfhi(oh) + bfhi(ol);
                    }
                    u32 hh = packbf(y0, y1);
                    u32 ll = packbf(y0 - bflo(hh), y1 - bfhi(hh));
                    *(u32*)(smc + off)         = hh;
                    *(u32*)(smc + XA_PL + off) = ll;
                }
        }
    };

    // ---- pipeline (with cross-GEMM prefetch chaining) ----
    gemmA<256>(smb, g_wimg + IMG_STEM, 4,
               g_wimg + IMG_BLK, 16384, true,
               acc, tid, lane, m0, nq, a_row, a_kh, ph);
    ep256(b_in, g_in, be_in, false);
    for (int b = 0; b < NBLK; ++b) {
        const unsigned char* nxt = (b < NBLK - 1)
            ? g_wimg + IMG_BLK + (size_t)(b + 1) * IMG_BLKSTR
            : g_wimg + IMG_HEAD;
        u32 ncb = (b < NBLK - 1) ? 16384u : 8192u;
        gemmA<256>(smb, g_wimg + IMG_BLK + (size_t)b * IMG_BLKSTR, 16,
                   nxt, ncb, false,
                   acc, tid, lane, m0, nq, a_row, a_kh, ph);
        ep256(bb + b * HID, gb + b * HID, betab + b * HID, true);
    }
    gemmA<128>(smb, g_wimg + IMG_HEAD, 16,
               nullptr, 0, false,
               acc, tid, lane, m0, nq, a_row, a_kh, ph);

    // ---- head epilogue: z = LN(.), write to g_z ----
    {
        const int n0 = nq * 32;
        float s1[4] = {0.f, 0.f, 0.f, 0.f}, s2[4] = {0.f, 0.f, 0.f, 0.f};
#pragma unroll
        for (int nt = 0; nt < 4; ++nt) {
            float2 bp = *(const float2*)&b_out[n0 + nt * 8 + qc * 2];
#pragma unroll
            for (int mt = 0; mt < 2; ++mt) {
                float* c = acc[mt][nt];
                c[0] += bp.x; c[1] += bp.y; c[2] += bp.x; c[3] += bp.y;
                s1[mt*2]   += c[0] + c[1];
                s2[mt*2]    = fmaf(c[0], c[0], fmaf(c[1], c[1], s2[mt*2]));
                s1[mt*2+1] += c[2] + c[3];
                s2[mt*2+1]  = fmaf(c[2], c[2], fmaf(c[3], c[3], s2[mt*2+1]));
            }
        }
#pragma unroll
        for (int r = 0; r < 4; ++r) {
            s1[r] += __shfl_xor_sync(0xffffffffu, s1[r], 1);
            s1[r] += __shfl_xor_sync(0xffffffffu, s1[r], 2);
            s2[r] += __shfl_xor_sync(0xffffffffu, s2[r], 1);
            s2[r] += __shfl_xor_sync(0xffffffffu, s2[r], 2);
        }
        __syncthreads();
        if (qc == 0) {
#pragma unroll
            for (int r = 0; r < 4; ++r) {
                int row = m0 + (r >> 1) * 16 + (r & 1) * 8 + qr;
                part[row * 4 + nq] = make_float2(s1[r], s2[r]);
            }
        }
        __syncthreads();
        float mu[4], rs[4];
#pragma unroll
        for (int r = 0; r < 4; ++r) {
            int row = m0 + (r >> 1) * 16 + (r & 1) * 8 + qr;
            float4 p0 = *(float4*)&part[row * 4];
            float4 p1 = *(float4*)&part[row * 4 + 2];
            float S1 = p0.x + p0.z + p1.x + p1.z;
            float S2 = p0.y + p0.w + p1.y + p1.w;
            float m_ = S1 * (1.f / 128.f);
            mu[r] = m_;
            rs[r] = rsqrtf(fmaf(-m_, m_, S2 * (1.f / 128.f)) + 1e-5f);
        }
        float* zbase = g_z + (size_t)g * (NODES * OUTD);
#pragma unroll
        for (int nt = 0; nt < 4; ++nt) {
            int col = n0 + nt * 8 + qc * 2;
            float2 gg = *(const float2*)&g_out[col];
            float2 ee = *(const float2*)&be_out[col];
#pragma unroll
            for (int mt = 0; mt < 2; ++mt)
#pragma unroll
                for (int h = 0; h < 2; ++h) {
                    int r4 = mt * 2 + h;
                    int row = m0 + mt * 16 + h * 8 + qr;
                    float z0 = fmaf((acc[mt][nt][2*h]   - mu[r4]) * rs[r4], gg.x, ee.x);
                    float z1 = fmaf((acc[mt][nt][2*h+1] - mu[r4]) * rs[r4], gg.y, ee.y);
                    *(float2*)(zbase + (size_t)(mh * 64 + row) * OUTD + col) =
                        make_float2(z0, z1);
                }
        }
    }
}

// ---------------- kernel B: Gram + distances + softmax + pool --------------
__global__ void __launch_bounds__(TPBB, 3)
pool(float* __restrict__ out)
{
    extern __shared__ __align__(16) unsigned char smc[];
    const u32 smb = s2u(smc);
    const int tid = threadIdx.x, lane = tid & 31, w = tid >> 5;
    const int qr = lane >> 2, qc = lane & 3;
    const int m0 = (w & 3) * 32, nh = w >> 2;
    const int n0 = nh * 64;
    const int grp = lane >> 3, ri = lane & 7;
    const int a_row = (grp & 1) * 8 + ri, a_kh = grp >> 1;
    const int b_n = (grp >> 1) * 8 + ri,  b_kh = grp & 1;
    const int g = blockIdx.x;

    float* sqf  = (float*)(smc + B_SQ);
    float* partf = (float*)(smc + B_PART);
    float* ssm  = (float*)(smc + B_SSM);
    float* wsm  = (float*)(smc + B_WSM);
    float* vpart = (float*)(smc + B_VP);

    // ---- load z, convert to hi/lo planes, row norms ----
    const float* zbase = g_z + (size_t)g * (NODES * OUTD);
#pragma unroll 1
    for (int j = 0; j < 16; ++j) {
        int r = w * 16 + j;
        float4 v = ((const float4*)(zbase + (size_t)r * OUTD))[lane];
        u32 h0 = packbf(v.x, v.y), h1 = packbf(v.z, v.w);
        u32 l0 = packbf(v.x - bflo(h0), v.y - bfhi(h0));
        u32 l1 = packbf(v.z - bflo(h1), v.w - bfhi(h1));
        u32 off = (u32)r * ZB_RS + (u32)lane * 8;
        *(u32*)(smc + off)             = h0;
        *(u32*)(smc + off + 4)         = h1;
        *(u32*)(smc + ZB_PL + off)     = l0;
        *(u32*)(smc + ZB_PL + off + 4) = l1;
        float sq = fmaf(v.x, v.x, fmaf(v.y, v.y, fmaf(v.z, v.z, v.w * v.w)));
        sq = warpsum(sq);
        if (lane == 0) sqf[r] = sq;
    }
    __syncthreads();

    // ---- Gram via bf16x3 mma (warp tile 32x64) ----
    float acc[2][8][4];
#pragma unroll
    for (int mt = 0; mt < 2; ++mt)
#pragma unroll
        for (int nt = 0; nt < 8; ++nt)
#pragma unroll
            for (int e = 0; e < 4; ++e) acc[mt][nt][e] = 0.f;

    const u32 azh = smb + (u32)(m0 + a_row) * ZB_RS + a_kh * 16;
    const u32 azl = azh + ZB_PL;
    const u32 bzh = smb + (u32)(n0 + b_n) * ZB_RS + b_kh * 16;
    const u32 bzl = bzh + ZB_PL;
#pragma unroll
    for (int ks = 0; ks < 8; ++ks) {
        const u32 kb = (u32)ks * 32;
        u32 ah0[4], ah1[4], al0[4], al1[4];
        ldsm4(ah0, azh + kb);
        ldsm4(ah1, azh + 16 * ZB_RS + kb);
        ldsm4(al0, azl + kb);
        ldsm4(al1, azl + 16 * ZB_RS + kb);
#pragma unroll
        for (int hf = 0; hf < 2; ++hf) {
            u32 bh[2][4], bl[2][4];
#pragma unroll
            for (int p = 0; p < 2; ++p) {
                const u32 wa = (u32)(hf * 2 + p) * 16 * ZB_RS + kb;
                ldsm4(bh[p], bzh + wa);
                ldsm4(bl[p], bzl + wa);
            }
#pragma unroll
            for (int p = 0; p < 2; ++p)
#pragma unroll
                for (int h = 0; h < 2; ++h) {
                    int nt = (hf * 2 + p) * 2 + h;
                    mma16816(acc[0][nt], ah0, bh[p][2*h], bh[p][2*h+1]);
                    mma16816(acc[1][nt], ah1, bh[p][2*h], bh[p][2*h+1]);
                }
#pragma unroll
            for (int p = 0; p < 2; ++p)
#pragma unroll
                for (int h = 0; h < 2; ++h) {
                    int nt = (hf * 2 + p) * 2 + h;
                    mma16816(acc[0][nt], al0, bh[p][2*h], bh[p][2*h+1]);
                    mma16816(acc[1][nt], al1, bh[p][2*h], bh[p][2*h+1]);
                }
#pragma unroll
            for (int p = 0; p < 2; ++p)
#pragma unroll
                for (int h = 0; h < 2; ++h) {
                    int nt = (hf * 2 + p) * 2 + h;
                    mma16816(acc[0][nt], ah0, bl[p][2*h], bl[p][2*h+1]);
                    mma16816(acc[1][nt], ah1, bl[p][2*h], bl[p][2*h+1]);
                }
        }
    }

    // ---- distances -> per-row sums ----
    float sa[4] = {0.f, 0.f, 0.f, 0.f};
#pragma unroll
    for (int nt = 0; nt < 8; ++nt) {
        int col = n0 + nt * 8 + qc * 2;
        float sc0 = sqf[col], sc1 = sqf[col + 1];
#pragma unroll
        for (int mt = 0; mt < 2; ++mt)
#pragma unroll
            for (int h = 0; h < 2; ++h) {
                int r4 = mt * 2 + h;
                int row = m0 + mt * 16 + h * 8 + qr;
                float sr = sqf[row];
                float d0 = sr + sc0 - 2.f * acc[mt][nt][2 * h];
                float d1 = sr + sc1 - 2.f * acc[mt][nt][2 * h + 1];
                float t0 = (col == row) ? 1e-6f : sqrtf(fmaxf(d0, 0.f) + 1e-12f);
                float t1 = (col + 1 == row) ? 1e-6f : sqrtf(fmaxf(d1, 0.f) + 1e-12f);
                sa[r4] += t0 + t1;
            }
    }
#pragma unroll
    for (int r = 0; r < 4; ++r) {
        sa[r] += __shfl_xor_sync(0xffffffffu, sa[r], 1);
        sa[r] += __shfl_xor_sync(0xffffffffu, sa[r], 2);
    }
    if (qc == 0) {
#pragma unroll
        for (int r = 0; r < 4; ++r) {
            int row = m0 + (r >> 1) * 16 + (r & 1) * 8 + qr;
            partf[row * 2 + nh] = sa[r];
        }
    }
    __syncthreads();
    if (tid < NODES)
        ssm[tid] = (partf[tid * 2] + partf[tid * 2 + 1]) * (1.f / 128.f);
    __syncthreads();

    // ---- softmax (warp 0) ----
    if (w == 0) {
        const float sc = 1.f / 0.25f;
        float sv[4], mx = -1e30f;
#pragma unroll
        for (int q = 0; q < 4; ++q) {
            sv[q] = ssm[lane + 32 * q] * sc;
            mx = fmaxf(mx, sv[q]);
        }
#pragma unroll
        for (int o = 16; o; o >>= 1)
            mx = fmaxf(mx, __shfl_xor_sync(0xffffffffu, mx, o));
        float e[4], se = 0.f;
#pragma unroll
        for (int q = 0; q < 4; ++q) { e[q] = expf(sv[q] - mx); se += e[q]; }
#pragma unroll
        for (int o = 16; o; o >>= 1) se += __shfl_xor_sync(0xffffffffu, se, o);
        float inv = 1.f / se;
#pragma unroll
        for (int q = 0; q < 4; ++q) {
            float ww = e[q] * inv;
            int i = lane + 32 * q;
            wsm[i] = ww;
            out[(size_t)NG * OUTD + (size_t)g * NODES + i] = ww;
        }
    }
    __syncthreads();

    // ---- pool: v[d] = sum_i w_i * (hi+lo)[i][d], split over 2 i-halves ----
    {
        int d = tid & 127, hseg = tid >> 7;
        float a = 0.f;
#pragma unroll 4
        for (int i = hseg * 64; i < hseg * 64 + 64; ++i) {
            u32 off = (u32)i * ZB_RS + (u32)d * 2;
            float zv = bf2f(*(unsigned short*)(smc + off))
                     + bf2f(*(unsigned short*)(smc + ZB_PL + off));
            a = fmaf(wsm[i], zv, a);
        }
        vpart[hseg * 128 + d] = a;
    }
    __syncthreads();
    if (tid < OUTD)
        out[(size_t)g * OUTD + tid] = vpart[tid] + vpart[128 + tid];
}

}  // namespace lb

extern "C" void kernel_launch(void* const* d_in, const int* in_sizes, int n_in,
                              void* d_out, int out_size)
{
    (void)in_sizes; (void)n_in; (void)out_size;
    const float* H     = (const float*)d_in[0];
    const float* W_in  = (const float*)d_in[2];
    const float* b_in  = (const float*)d_in[3];
    const float* g_in  = (const float*)d_in[4];
    const float* be_in = (const float*)d_in[5];
    const float* Wb    = (const float*)d_in[6];
    const float* bb    = (const float*)d_in[7];
    const float* gb    = (const float*)d_in[8];
    const float* betab = (const float*)d_in[9];
    const float* W_out = (const float*)d_in[10];
    const float* b_out = (const float*)d_in[11];
    const float* g_out = (const float*)d_in[12];
    const float* be_out= (const float*)d_in[13];
    float* out = (float*)d_out;

    lb::prep<<<960, 256>>>(W_in, Wb, W_out);

    cudaFuncSetAttribute(lb::mlp,
                         cudaFuncAttributeMaxDynamicSharedMemorySize,
                         lb::SMEM_A);
    cudaFuncSetAttribute(lb::pool,
                         cudaFuncAttributeMaxDynamicSharedMemorySize,
                         lb::SMEM_B);

    lb::mlp<<<2 * lb::NG, lb::TPA, lb::SMEM_A>>>(
        H, b_in, g_in, be_in, bb, gb, betab, b_out, g_out, be_out);
    lb::pool<<<lb::NG, lb::TPBB, lb::SMEM_B>>>(out);
}

// round 13
// speedup vs baseline: 1.0180x; 1.0180x over previous
#include <cuda_runtime.h>
#include <cuda_bf16.h>
#include <cstdint>

// ============================================================================
// LocalBranch round 13: R11 base (542us) + fused pool (last-CTA-of-pair runs
// Gram+softmax+pool inline -> no serial pool-kernel tail) + wave-slot stagger
// (de-lockstep the 2 co-resident CTAs so epilogues overlap the peer's MMAs).
//  mlp: 2048 CTAs x 256 thr, 64 nodes each, bf16x3 mma.sync, tile-packed k16
//  chunks via 2-slot cp.async.bulk ring; z -> g_z; 2nd finisher pools.
// ============================================================================

namespace lb {

using u32 = uint32_t;

constexpr int NODES = 128, IND = 64, HID = 256, OUTD = 128, NBLK = 3, NG = 1024;

// ---- mlp smem ----
constexpr int TPA   = 256;
constexpr int XA_RS = 528;               // x-plane row stride (bytes)
constexpr int XA_PL = 64 * XA_RS;        // 33792 per plane (64 rows)
constexpr int A_RING = 2 * XA_PL;        // 67584
constexpr int A_SLOTB = 16384;           // max chunk bytes (N=256)
constexpr int A_PART = A_RING + 2 * A_SLOTB;   // 100352: float2[64*4]
constexpr int A_MB   = A_PART + 2048;    // 102400: 2 mbarriers
constexpr int SMEM_A = A_MB + 48;        // 102448 (x2 = 204896 <= 228KB)

// ---- pool-phase smem overlay (inside the same allocation) ----
constexpr int ZB_RS = 272;               // z-plane row stride (bytes)
constexpr int ZB_PL = 128 * ZB_RS;       // 34816 per plane
constexpr int B_SQ   = 2 * ZB_PL;        // 69632: float[128]
constexpr int B_PART = B_SQ + 512;       // float[256]
constexpr int B_SSM  = B_PART + 1024;    // float[128]
constexpr int B_WSM  = B_SSM + 512;      // float[128]
constexpr int B_VP   = B_WSM + 512;      // float[256]  (ends 73216 < SMEM_A)

// ---- weight image: k16 chunks of ldsm-ready 128B tiles (see prep) ----
constexpr long IMG_STEM   = 0;                    // 4 chunks x 16384
constexpr long IMG_BLK    = 65536;                // 3 x 16 x 16384
constexpr long IMG_BLKSTR = 262144;
constexpr long IMG_HEAD   = 851968;               // 16 x 8192
__device__ __align__(128) unsigned char g_wimg[983040];
__device__ float g_z[(size_t)NG * NODES * OUTD];  // 64 MB scratch
__device__ unsigned int g_cnt[NG];                // per-graph finish counter

// ---------------- PTX helpers ----------------
__device__ __forceinline__ u32 s2u(const void* p) {
    u32 a;
    asm("{ .reg .u64 t; cvta.to.shared.u64 t, %1; cvt.u32.u64 %0, t; }"
        : "=r"(a) : "l"(p));
    return a;
}
__device__ __forceinline__ void ldsm4(u32* r, u32 addr) {
    asm volatile("ldmatrix.sync.aligned.m8n8.x4.shared.b16 {%0,%1,%2,%3}, [%4];"
                 : "=r"(r[0]), "=r"(r[1]), "=r"(r[2]), "=r"(r[3]) : "r"(addr));
}
__device__ __forceinline__ void mma16816(float* c, const u32* a, u32 b0, u32 b1) {
    asm volatile(
        "mma.sync.aligned.m16n8k16.row.col.f32.bf16.bf16.f32 "
        "{%0,%1,%2,%3}, {%4,%5,%6,%7}, {%8,%9}, {%0,%1,%2,%3};"
        : "+f"(c[0]), "+f"(c[1]), "+f"(c[2]), "+f"(c[3])
        : "r"(a[0]), "r"(a[1]), "r"(a[2]), "r"(a[3]), "r"(b0), "r"(b1));
}
__device__ __forceinline__ void mbar_init(u32 mb, u32 c) {
    asm volatile("mbarrier.init.shared.b64 [%0], %1;" :: "r"(mb), "r"(c)
                 : "memory");
}
__device__ __forceinline__ void mbar_expect_tx(u32 mb, u32 tx) {
    asm volatile("mbarrier.arrive.expect_tx.shared.b64 _, [%0], %1;"
                 :: "r"(mb), "r"(tx) : "memory");
}
__device__ __forceinline__ void bulk_g2s(u32 dst, const void* src, u32 bytes,
                                         u32 mb) {
    asm volatile(
        "cp.async.bulk.shared::cta.global.mbarrier::complete_tx::bytes "
        "[%0], [%1], %2, [%3];"
        :: "r"(dst), "l"(src), "r"(bytes), "r"(mb) : "memory");
}
__device__ __forceinline__ void mbar_wait(u32 mb, u32 parity) {
    asm volatile(
        "{\n\t.reg .pred P;\n\t"
        "W%=:\n\t"
        "mbarrier.try_wait.parity.acquire.cta.shared::cta.b64 P, [%0], %1, 0x989680;\n\t"
        "@!P bra W%=;\n\t}"
        :: "r"(mb), "r"(parity) : "memory");
}

// ---------------- bf16 pack helpers ----------------
__device__ __forceinline__ u32 packbf(float x0, float x1) {
    unsigned short a = __bfloat16_as_ushort(__float2bfloat16(x0));
    unsigned short b = __bfloat16_as_ushort(__float2bfloat16(x1));
    return (u32)a | ((u32)b << 16);
}
__device__ __forceinline__ float bflo(u32 p) {
    return __bfloat162float(__ushort_as_bfloat16((unsigned short)(p & 0xffff)));
}
__device__ __forceinline__ float bfhi(u32 p) {
    return __bfloat162float(__ushort_as_bfloat16((unsigned short)(p >> 16)));
}
__device__ __forceinline__ float bf2f(unsigned short v) {
    return __bfloat162float(__ushort_as_bfloat16(v));
}
__device__ __forceinline__ float warpsum(float v) {
#pragma unroll
    for (int o = 16; o; o >>= 1) v += __shfl_xor_sync(0xffffffffu, v, o);
    return v;
}

// ---------------- prep: weights -> split, tile-packed image; zero g_cnt ----
__global__ void prep(const float* __restrict__ Wi, const float* __restrict__ Wb,
                     const float* __restrict__ Wo) {
    int idx = blockIdx.x * 256 + threadIdx.x;        // 245760 total
    if (idx < NG) g_cnt[idx] = 0u;
    const float* W; int k, n, N; long base;
    if (idx < 16384) {
        W = Wi; N = 256; k = idx >> 8; n = idx & 255; base = IMG_STEM;
    } else if (idx < 212992) {
        int e = idx - 16384; int b = e >> 16; e &= 65535;
        W = Wb + (size_t)b * 65536; N = 256; k = e >> 8; n = e & 255;
        base = IMG_BLK + (long)b * IMG_BLKSTR;
    } else {
        int e = idx - 212992;
        W = Wo; N = 128; k = e >> 7; n = e & 127; base = IMG_HEAD;
    }
    float w = W[(size_t)k * N + n];
    __nv_bfloat16 h = __float2bfloat16(w);
    __nv_bfloat16 l = __float2bfloat16(w - __bfloat162float(h));
    int kk = k & 15;
    long off = base + (long)(k >> 4) * ((long)N * 64)
             + (long)(n >> 4) * 512
             + (long)((((n >> 3) & 1) * 2 + (kk >> 3)) * 128)
             + (n & 7) * 16 + (kk & 7) * 2;
    *(__nv_bfloat16*)(g_wimg + off) = h;
    *(__nv_bfloat16*)(g_wimg + off + (long)N * 32) = l;
}

// ---------------- staged GEMM (bulk ring, per-GEMM staging as in R11) ------
template<int N>   // 256 or 128
__device__ __forceinline__ void gemmA(
    u32 smb, const unsigned char* img, int nchunk,
    float (&acc)[2][8][4], int tid, int lane, int m0, int nq,
    int a_row, int a_kh, int (&ph)[2])
{
    constexpr int NH = N / 128;            // n16-pair groups per warp (2|1)
    constexpr u32 CB = (u32)N * 64;        // chunk bytes (2 planes)
    const int n16b = nq * (N / 64);        // first n16 index for this warp

    const u32 axh = smb + (u32)(m0 + a_row) * XA_RS + a_kh * 16;
    const u32 axl = axh + XA_PL;
    const u32 mb0 = smb + A_MB;

#pragma unroll
    for (int mt = 0; mt < 2; ++mt)
#pragma unroll
        for (int nt = 0; nt < 8; ++nt)
#pragma unroll
            for (int e = 0; e < 4; ++e) acc[mt][nt][e] = 0.f;

    __syncthreads();   // prior slot readers + plane writers done
    if (tid == 0) {
        mbar_expect_tx(mb0, CB);
        bulk_g2s(smb + A_RING, img, CB, mb0);
        mbar_expect_tx(mb0 + 8, CB);
        bulk_g2s(smb + A_RING + A_SLOTB, img + CB, CB, mb0 + 8);
    }

    for (int ch = 0; ch < nchunk; ++ch) {
        const int s = ch & 1;
        mbar_wait(mb0 + 8 * s, (u32)ph[s]);
        ph[s] ^= 1;
        const u32 slot = smb + A_RING + (u32)s * A_SLOTB;
        const u32 kb = (u32)ch * 32;       // 16 k-values = 32 B in x planes

        u32 ah0[4], ah1[4], al0[4], al1[4];
        ldsm4(ah0, axh + kb);
        ldsm4(ah1, axh + 16 * XA_RS + kb);
        ldsm4(al0, axl + kb);
        ldsm4(al1, axl + 16 * XA_RS + kb);
#pragma unroll
        for (int hf = 0; hf < NH; ++hf) {
            u32 bh[2][4], bl[2][4];
#pragma unroll
            for (int p = 0; p < 2; ++p) {
                const u32 wa = slot + (u32)(n16b + hf * 2 + p) * 512
                             + (u32)lane * 16;
                ldsm4(bh[p], wa);
                ldsm4(bl[p], wa + (u32)N * 32);
            }
            // term 1: Ahi * Bhi
#pragma unroll
            for (int p = 0; p < 2; ++p)
#pragma unroll
                for (int h = 0; h < 2; ++h) {
                    int nt = (hf * 2 + p) * 2 + h;
                    mma16816(acc[0][nt], ah0, bh[p][2*h], bh[p][2*h+1]);
                    mma16816(acc[1][nt], ah1, bh[p][2*h], bh[p][2*h+1]);
                }
            // term 2: Alo * Bhi
#pragma unroll
            for (int p = 0; p < 2; ++p)
#pragma unroll
                for (int h = 0; h < 2; ++h) {
                    int nt = (hf * 2 + p) * 2 + h;
                    mma16816(acc[0][nt], al0, bh[p][2*h], bh[p][2*h+1]);
                    mma16816(acc[1][nt], al1, bh[p][2*h], bh[p][2*h+1]);
                }
            // term 3: Ahi * Blo
#pragma unroll
            for (int p = 0; p < 2; ++p)
#pragma unroll
                for (int h = 0; h < 2; ++h) {
                    int nt = (hf * 2 + p) * 2 + h;
                    mma16816(acc[0][nt], ah0, bl[p][2*h], bl[p][2*h+1]);
                    mma16816(acc[1][nt], ah1, bl[p][2*h], bl[p][2*h+1]);
                }
        }
        if (ch + 2 < nchunk) {
            __syncthreads();   // all warps done reading slot s
            if (tid == 0) {
                mbar_expect_tx(mb0 + 8 * s, CB);
                bulk_g2s(slot, img + (size_t)(ch + 2) * CB, CB, mb0 + 8 * s);
            }
        }
    }
}

// ---------------- mlp (+ fused pool on second finisher) ----------------
__global__ void __launch_bounds__(TPA, 2)
mlp(const float* __restrict__ H,
    const float* __restrict__ b_in, const float* __restrict__ g_in,
    const float* __restrict__ be_in,
    const float* __restrict__ bb, const float* __restrict__ gb,
    const float* __restrict__ betab,
    const float* __restrict__ b_out, const float* __restrict__ g_out,
    const float* __restrict__ be_out,
    float* __restrict__ out)
{
    extern __shared__ __align__(128) unsigned char smc[];
    __shared__ unsigned int s_flag;
    const u32 smb = s2u(smc);
    const int tid = threadIdx.x, lane = tid & 31, w = tid >> 5;
    const int qr = lane >> 2, qc = lane & 3;
    const int m0 = (w & 1) * 32, nq = w >> 1;
    const int grp = lane >> 3, ri = lane & 7;
    const int a_row = (grp & 1) * 8 + ri, a_kh = grp >> 1;
    const int g = blockIdx.x >> 1, mh = blockIdx.x & 1;

    float2* part = (float2*)(smc + A_PART);
    int ph[2] = {0, 0};

    if (tid == 0) {
        mbar_init(smb + A_MB, 1);
        mbar_init(smb + A_MB + 8, 1);
    }

    // ---- stagger: de-lockstep the two co-resident CTAs (wave-slot parity).
    if (((blockIdx.x / 148) & 1) != 0) {
        long long t0 = clock64();
        while (clock64() - t0 < 6000) {}
    }

    // ---- load H (64 rows, node base mh*64) -> hi/lo planes ----
    {
        const int row = tid >> 2, c4 = tid & 3;
        const float4* hs = (const float4*)(H + (size_t)g * NODES * IND
                                           + (size_t)(mh * 64 + row) * IND
                                           + c4 * 16);
        const u32 off = (u32)row * XA_RS + (u32)c4 * 32;
#pragma unroll
        for (int q = 0; q < 4; ++q) {
            float4 v = hs[q];
            u32 h0 = packbf(v.x, v.y), h1 = packbf(v.z, v.w);
            u32 l0 = packbf(v.x - bflo(h0), v.y - bfhi(h0));
            u32 l1 = packbf(v.z - bflo(h1), v.w - bfhi(h1));
            *(u32*)(smc + off + q * 8)             = h0;
            *(u32*)(smc + off + q * 8 + 4)         = h1;
            *(u32*)(smc + XA_PL + off + q * 8)     = l0;
            *(u32*)(smc + XA_PL + off + q * 8 + 4) = l1;
        }
    }

    float acc[2][8][4];

    // ---- LN(+relu,+residual) epilogue N=256, rewrites x planes ----
    auto ep256 = [&](const float* bias, const float* gam, const float* bet,
                     bool res) {
        const int n0 = nq * 64;
        float s1[4] = {0.f, 0.f, 0.f, 0.f}, s2[4] = {0.f, 0.f, 0.f, 0.f};
#pragma unroll
        for (int nt = 0; nt < 8; ++nt) {
            float2 bp = *(const float2*)&bias[n0 + nt * 8 + qc * 2];
#pragma unroll
            for (int mt = 0; mt < 2; ++mt) {
                float* c = acc[mt][nt];
                c[0] += bp.x; c[1] += bp.y; c[2] += bp.x; c[3] += bp.y;
                s1[mt*2]   += c[0] + c[1];
                s2[mt*2]    = fmaf(c[0], c[0], fmaf(c[1], c[1], s2[mt*2]));
                s1[mt*2+1] += c[2] + c[3];
                s2[mt*2+1]  = fmaf(c[2], c[2], fmaf(c[3], c[3], s2[mt*2+1]));
            }
        }
#pragma unroll
        for (int r = 0; r < 4; ++r) {
            s1[r] += __shfl_xor_sync(0xffffffffu, s1[r], 1);
            s1[r] += __shfl_xor_sync(0xffffffffu, s1[r], 2);
            s2[r] += __shfl_xor_sync(0xffffffffu, s2[r], 1);
            s2[r] += __shfl_xor_sync(0xffffffffu, s2[r], 2);
        }
        __syncthreads();
        if (qc == 0) {
#pragma unroll
            for (int r = 0; r < 4; ++r) {
                int row = m0 + (r >> 1) * 16 + (r & 1) * 8 + qr;
                part[row * 4 + nq] = make_float2(s1[r], s2[r]);
            }
        }
        __syncthreads();
        float mu[4], rs[4];
#pragma unroll
        for (int r = 0; r < 4; ++r) {
            int row = m0 + (r >> 1) * 16 + (r & 1) * 8 + qr;
            float4 p0 = *(float4*)&part[row * 4];
            float4 p1 = *(float4*)&part[row * 4 + 2];
            float S1 = p0.x + p0.z + p1.x + p1.z;
            float S2 = p0.y + p0.w + p1.y + p1.w;
            float m_ = S1 * (1.f / 256.f);
            mu[r] = m_;
            rs[r] = rsqrtf(fmaf(-m_, m_, S2 * (1.f / 256.f)) + 1e-5f);
        }
        __syncthreads();
#pragma unroll
        for (int nt = 0; nt < 8; ++nt) {
            int col = n0 + nt * 8 + qc * 2;
            float2 gg = *(const float2*)&gam[col];
            float2 ee = *(const float2*)&bet[col];
#pragma unroll
            for (int mt = 0; mt < 2; ++mt)
#pragma unroll
                for (int h = 0; h < 2; ++h) {
                    int r4 = mt * 2 + h;
                    int row = m0 + mt * 16 + h * 8 + qr;
                    float v0 = acc[mt][nt][2 * h], v1 = acc[mt][nt][2 * h + 1];
                    float y0 = fmaxf(fmaf((v0 - mu[r4]) * rs[r4], gg.x, ee.x), 0.f);
                    float y1 = fmaxf(fmaf((v1 - mu[r4]) * rs[r4], gg.y, ee.y), 0.f);
                    u32 off = (u32)row * XA_RS + (u32)col * 2;
                    if (res) {
                        u32 oh = *(u32*)(smc + off);
                        u32 ol = *(u32*)(smc + XA_PL + off);
                        y0 += bflo(oh) + bflo(ol);
                        y1 += bfhi(oh) + bfhi(ol);
                    }
                    u32 hh = packbf(y0, y1);
                    u32 ll = packbf(y0 - bflo(hh), y1 - bfhi(hh));
                    *(u32*)(smc + off)         = hh;
                    *(u32*)(smc + XA_PL + off) = ll;
                }
        }
    };

    // ---- pipeline ----
    gemmA<256>(smb, g_wimg + IMG_STEM, 4, acc, tid, lane, m0, nq,
               a_row, a_kh, ph);
    ep256(b_in, g_in, be_in, false);
    for (int b = 0; b < NBLK; ++b) {
        gemmA<256>(smb, g_wimg + IMG_BLK + (size_t)b * IMG_BLKSTR, 16,
                   acc, tid, lane, m0, nq, a_row, a_kh, ph);
        ep256(bb + b * HID, gb + b * HID, betab + b * HID, true);
    }
    gemmA<128>(smb, g_wimg + IMG_HEAD, 16, acc, tid, lane, m0, nq,
               a_row, a_kh, ph);

    // ---- head epilogue: z = LN(.), write to g_z ----
    {
        const int n0 = nq * 32;
        float s1[4] = {0.f, 0.f, 0.f, 0.f}, s2[4] = {0.f, 0.f, 0.f, 0.f};
#pragma unroll
        for (int nt = 0; nt < 4; ++nt) {
            float2 bp = *(const float2*)&b_out[n0 + nt * 8 + qc * 2];
#pragma unroll
            for (int mt = 0; mt < 2; ++mt) {
                float* c = acc[mt][nt];
                c[0] += bp.x; c[1] += bp.y; c[2] += bp.x; c[3] += bp.y;
                s1[mt*2]   += c[0] + c[1];
                s2[mt*2]    = fmaf(c[0], c[0], fmaf(c[1], c[1], s2[mt*2]));
                s1[mt*2+1] += c[2] + c[3];
                s2[mt*2+1]  = fmaf(c[2], c[2], fmaf(c[3], c[3], s2[mt*2+1]));
            }
        }
#pragma unroll
        for (int r = 0; r < 4; ++r) {
            s1[r] += __shfl_xor_sync(0xffffffffu, s1[r], 1);
            s1[r] += __shfl_xor_sync(0xffffffffu, s1[r], 2);
            s2[r] += __shfl_xor_sync(0xffffffffu, s2[r], 1);
            s2[r] += __shfl_xor_sync(0xffffffffu, s2[r], 2);
        }
        __syncthreads();
        if (qc == 0) {
#pragma unroll
            for (int r = 0; r < 4; ++r) {
                int row = m0 + (r >> 1) * 16 + (r & 1) * 8 + qr;
                part[row * 4 + nq] = make_float2(s1[r], s2[r]);
            }
        }
        __syncthreads();
        float mu[4], rs[4];
#pragma unroll
        for (int r = 0; r < 4; ++r) {
            int row = m0 + (r >> 1) * 16 + (r & 1) * 8 + qr;
            float4 p0 = *(float4*)&part[row * 4];
            float4 p1 = *(float4*)&part[row * 4 + 2];
            float S1 = p0.x + p0.z + p1.x + p1.z;
            float S2 = p0.y + p0.w + p1.y + p1.w;
            float m_ = S1 * (1.f / 128.f);
            mu[r] = m_;
            rs[r] = rsqrtf(fmaf(-m_, m_, S2 * (1.f / 128.f)) + 1e-5f);
        }
        float* zbase = g_z + (size_t)g * (NODES * OUTD);
#pragma unroll
        for (int nt = 0; nt < 4; ++nt) {
            int col = n0 + nt * 8 + qc * 2;
            float2 gg = *(const float2*)&g_out[col];
            float2 ee = *(const float2*)&be_out[col];
#pragma unroll
            for (int mt = 0; mt < 2; ++mt)
#pragma unroll
                for (int h = 0; h < 2; ++h) {
                    int r4 = mt * 2 + h;
                    int row = m0 + mt * 16 + h * 8 + qr;
                    float z0 = fmaf((acc[mt][nt][2*h]   - mu[r4]) * rs[r4], gg.x, ee.x);
                    float z1 = fmaf((acc[mt][nt][2*h+1] - mu[r4]) * rs[r4], gg.y, ee.y);
                    *(float2*)(zbase + (size_t)(mh * 64 + row) * OUTD + col) =
                        make_float2(z0, z1);
                }
        }
    }

    // ---- handoff: second finisher of the graph pair runs the pool ----
    __syncthreads();
    if (tid == 0) {
        __threadfence();                       // publish this CTA's z
        unsigned int old = atomicAdd(&g_cnt[g], 1u);
        s_flag = old;                          // 1 -> we are second
    }
    __syncthreads();
    if (s_flag != 1u) return;
    __threadfence();                           // acquire peer CTA's z

    // ================== fused pool (Gram + softmax + weighted sum) =========
    {
        const int m0p = (w & 3) * 32, nh = w >> 2;
        const int n0p = nh * 64;

        float* sqf   = (float*)(smc + B_SQ);
        float* partf = (float*)(smc + B_PART);
        float* ssm   = (float*)(smc + B_SSM);
        float* wsm   = (float*)(smc + B_WSM);
        float* vpart = (float*)(smc + B_VP);

        // ---- load z, convert to hi/lo planes, row norms ----
        const float* zbase = g_z + (size_t)g * (NODES * OUTD);
#pragma unroll 1
        for (int j = 0; j < 16; ++j) {
            int r = w * 16 + j;
            float4 v = ((const float4*)(zbase + (size_t)r * OUTD))[lane];
            u32 h0 = packbf(v.x, v.y), h1 = packbf(v.z, v.w);
            u32 l0 = packbf(v.x - bflo(h0), v.y - bfhi(h0));
            u32 l1 = packbf(v.z - bflo(h1), v.w - bfhi(h1));
            u32 off = (u32)r * ZB_RS + (u32)lane * 8;
            *(u32*)(smc + off)             = h0;
            *(u32*)(smc + off + 4)         = h1;
            *(u32*)(smc + ZB_PL + off)     = l0;
            *(u32*)(smc + ZB_PL + off + 4) = l1;
            float sq = fmaf(v.x, v.x, fmaf(v.y, v.y, fmaf(v.z, v.z, v.w * v.w)));
            sq = warpsum(sq);
            if (lane == 0) sqf[r] = sq;
        }
        __syncthreads();

        // ---- Gram via bf16x3 mma (warp tile 32x64) ----
        float acc2[2][8][4];
#pragma unroll
        for (int mt = 0; mt < 2; ++mt)
#pragma unroll
            for (int nt = 0; nt < 8; ++nt)
#pragma unroll
                for (int e = 0; e < 4; ++e) acc2[mt][nt][e] = 0.f;

        const int b_n = (grp >> 1) * 8 + ri, b_kh = grp & 1;
        const u32 azh = smb + (u32)(m0p + a_row) * ZB_RS + a_kh * 16;
        const u32 azl = azh + ZB_PL;
        const u32 bzh = smb + (u32)(n0p + b_n) * ZB_RS + b_kh * 16;
        const u32 bzl = bzh + ZB_PL;
#pragma unroll
        for (int ks = 0; ks < 8; ++ks) {
            const u32 kb = (u32)ks * 32;
            u32 ah0[4], ah1[4], al0[4], al1[4];
            ldsm4(ah0, azh + kb);
            ldsm4(ah1, azh + 16 * ZB_RS + kb);
            ldsm4(al0, azl + kb);
            ldsm4(al1, azl + 16 * ZB_RS + kb);
#pragma unroll
            for (int hf = 0; hf < 2; ++hf) {
                u32 bh[2][4], bl[2][4];
#pragma unroll
                for (int p = 0; p < 2; ++p) {
                    const u32 wa = (u32)(hf * 2 + p) * 16 * ZB_RS + kb;
                    ldsm4(bh[p], bzh + wa);
                    ldsm4(bl[p], bzl + wa);
                }
#pragma unroll
                for (int p = 0; p < 2; ++p)
#pragma unroll
                    for (int h = 0; h < 2; ++h) {
                        int nt = (hf * 2 + p) * 2 + h;
                        mma16816(acc2[0][nt], ah0, bh[p][2*h], bh[p][2*h+1]);
                        mma16816(acc2[1][nt], ah1, bh[p][2*h], bh[p][2*h+1]);
                    }
#pragma unroll
                for (int p = 0; p < 2; ++p)
#pragma unroll
                    for (int h = 0; h < 2; ++h) {
                        int nt = (hf * 2 + p) * 2 + h;
                        mma16816(acc2[0][nt], al0, bh[p][2*h], bh[p][2*h+1]);
                        mma16816(acc2[1][nt], al1, bh[p][2*h], bh[p][2*h+1]);
                    }
#pragma unroll
                for (int p = 0; p < 2; ++p)
#pragma unroll
                    for (int h = 0; h < 2; ++h) {
                        int nt = (hf * 2 + p) * 2 + h;
                        mma16816(acc2[0][nt], ah0, bl[p][2*h], bl[p][2*h+1]);
                        mma16816(acc2[1][nt], ah1, bl[p][2*h], bl[p][2*h+1]);
                    }
            }
        }

        // ---- distances -> per-row sums ----
        float sa[4] = {0.f, 0.f, 0.f, 0.f};
#pragma unroll
        for (int nt = 0; nt < 8; ++nt) {
            int col = n0p + nt * 8 + qc * 2;
            float sc0 = sqf[col], sc1 = sqf[col + 1];
#pragma unroll
            for (int mt = 0; mt < 2; ++mt)
#pragma unroll
                for (int h = 0; h < 2; ++h) {
                    int r4 = mt * 2 + h;
                    int row = m0p + mt * 16 + h * 8 + qr;
                    float sr = sqf[row];
                    float d0 = sr + sc0 - 2.f * acc2[mt][nt][2 * h];
                    float d1 = sr + sc1 - 2.f * acc2[mt][nt][2 * h + 1];
                    float t0 = (col == row) ? 1e-6f
                               : sqrtf(fmaxf(d0, 0.f) + 1e-12f);
                    float t1 = (col + 1 == row) ? 1e-6f
                               : sqrtf(fmaxf(d1, 0.f) + 1e-12f);
                    sa[r4] += t0 + t1;
                }
        }
#pragma unroll
        for (int r = 0; r < 4; ++r) {
            sa[r] += __shfl_xor_sync(0xffffffffu, sa[r], 1);
            sa[r] += __shfl_xor_sync(0xffffffffu, sa[r], 2);
        }
        if (qc == 0) {
#pragma unroll
            for (int r = 0; r < 4; ++r) {
                int row = m0p + (r >> 1) * 16 + (r & 1) * 8 + qr;
                partf[row * 2 + nh] = sa[r];
            }
        }
        __syncthreads();
        if (tid < NODES)
            ssm[tid] = (partf[tid * 2] + partf[tid * 2 + 1]) * (1.f / 128.f);
        __syncthreads();

        // ---- softmax (warp 0) ----
        if (w == 0) {
            const float sc = 1.f / 0.25f;
            float sv[4], mx = -1e30f;
#pragma unroll
            for (int q = 0; q < 4; ++q) {
                sv[q] = ssm[lane + 32 * q] * sc;
                mx = fmaxf(mx, sv[q]);
            }
#pragma unroll
            for (int o = 16; o; o >>= 1)
                mx = fmaxf(mx, __shfl_xor_sync(0xffffffffu, mx, o));
            float e[4], se = 0.f;
#pragma unroll
            for (int q = 0; q < 4; ++q) { e[q] = expf(sv[q] - mx); se += e[q]; }
#pragma unroll
            for (int o = 16; o; o >>= 1)
                se += __shfl_xor_sync(0xffffffffu, se, o);
            float inv = 1.f / se;
#pragma unroll
            for (int q = 0; q < 4; ++q) {
                float ww = e[q] * inv;
                int i = lane + 32 * q;
                wsm[i] = ww;
                out[(size_t)NG * OUTD + (size_t)g * NODES + i] = ww;
            }
        }
        __syncthreads();

        // ---- pool: v[d] = sum_i w_i * (hi+lo)[i][d], 2 i-halves ----
        {
            int d = tid & 127, hseg = tid >> 7;
            float a = 0.f;
#pragma unroll 4
            for (int i = hseg * 64; i < hseg * 64 + 64; ++i) {
                u32 off = (u32)i * ZB_RS + (u32)d * 2;
                float zv = bf2f(*(unsigned short*)(smc + off))
                         + bf2f(*(unsigned short*)(smc + ZB_PL + off));
                a = fmaf(wsm[i], zv, a);
            }
            vpart[hseg * 128 + d] = a;
        }
        __syncthreads();
        if (tid < OUTD)
            out[(size_t)g * OUTD + tid] = vpart[tid] + vpart[128 + tid];
    }
}

}  // namespace lb

extern "C" void kernel_launch(void* const* d_in, const int* in_sizes, int n_in,
                              void* d_out, int out_size)
{
    (void)in_sizes; (void)n_in; (void)out_size;
    const float* H     = (const float*)d_in[0];
    const float* W_in  = (const float*)d_in[2];
    const float* b_in  = (const float*)d_in[3];
    const float* g_in  = (const float*)d_in[4];
    const float* be_in = (const float*)d_in[5];
    const float* Wb    = (const float*)d_in[6];
    const float* bb    = (const float*)d_in[7];
    const float* gb    = (const float*)d_in[8];
    const float* betab = (const float*)d_in[9];
    const float* W_out = (const float*)d_in[10];
    const float* b_out = (const float*)d_in[11];
    const float* g_out = (const float*)d_in[12];
    const float* be_out= (const float*)d_in[13];
    float* out = (float*)d_out;

    lb::prep<<<960, 256>>>(W_in, Wb, W_out);

    cudaFuncSetAttribute(lb::mlp,
                         cudaFuncAttributeMaxDynamicSharedMemorySize,
                         lb::SMEM_A);

    lb::mlp<<<2 * lb::NG, lb::TPA, lb::SMEM_A>>>(
        H, b_in, g_in, be_in, bb, gb, betab, b_out, g_out, be_out, out);
}

// round 14
// speedup vs baseline: 1.0536x; 1.0350x over previous
#include <cuda_runtime.h>
#include <cuda_bf16.h>
#include <cstdint>

// ============================================================================
// LocalBranch round 14: R13 base (539us), scalar-instruction diet:
//  - all bf16 pack/unpack via cvt.rn.bf16x2.f32 / bf16x2->f32x2 intrinsics
//    (halves conversion instruction count in epilogues, H-load, pool)
//  - stagger spin removed (measured neutral)
//  mlp: 2048 CTAs x 256 thr, 64 nodes each, bf16x3 mma.sync, tile-packed k16
//  chunks via 2-slot cp.async.bulk ring; z -> g_z; 2nd finisher pools inline.
// ============================================================================

namespace lb {

using u32 = uint32_t;

constexpr int NODES = 128, IND = 64, HID = 256, OUTD = 128, NBLK = 3, NG = 1024;

// ---- mlp smem ----
constexpr int TPA   = 256;
constexpr int XA_RS = 528;               // x-plane row stride (bytes)
constexpr int XA_PL = 64 * XA_RS;        // 33792 per plane (64 rows)
constexpr int A_RING = 2 * XA_PL;        // 67584
constexpr int A_SLOTB = 16384;           // max chunk bytes (N=256)
constexpr int A_PART = A_RING + 2 * A_SLOTB;   // 100352: float2[64*4]
constexpr int A_MB   = A_PART + 2048;    // 102400: 2 mbarriers
constexpr int SMEM_A = A_MB + 48;        // 102448 (x2 = 204896 <= 228KB)

// ---- pool-phase smem overlay ----
constexpr int ZB_RS = 272;               // z-plane row stride (bytes)
constexpr int ZB_PL = 128 * ZB_RS;       // 34816 per plane
constexpr int B_SQ   = 2 * ZB_PL;        // 69632: float[128]
constexpr int B_PART = B_SQ + 512;       // float[256]
constexpr int B_SSM  = B_PART + 1024;    // float[128]
constexpr int B_WSM  = B_SSM + 512;      // float[128]
constexpr int B_VP   = B_WSM + 512;      // float[256] (ends 73216 < SMEM_A)

// ---- weight image: k16 chunks of ldsm-ready 128B tiles (see prep) ----
constexpr long IMG_STEM   = 0;                    // 4 chunks x 16384
constexpr long IMG_BLK    = 65536;                // 3 x 16 x 16384
constexpr long IMG_BLKSTR = 262144;
constexpr long IMG_HEAD   = 851968;               // 16 x 8192
__device__ __align__(128) unsigned char g_wimg[983040];
__device__ float g_z[(size_t)NG * NODES * OUTD];  // 64 MB scratch
__device__ unsigned int g_cnt[NG];                // per-graph finish counter

// ---------------- PTX helpers ----------------
__device__ __forceinline__ u32 s2u(const void* p) {
    u32 a;
    asm("{ .reg .u64 t; cvta.to.shared.u64 t, %1; cvt.u32.u64 %0, t; }"
        : "=r"(a) : "l"(p));
    return a;
}
__device__ __forceinline__ void ldsm4(u32* r, u32 addr) {
    asm volatile("ldmatrix.sync.aligned.m8n8.x4.shared.b16 {%0,%1,%2,%3}, [%4];"
                 : "=r"(r[0]), "=r"(r[1]), "=r"(r[2]), "=r"(r[3]) : "r"(addr));
}
__device__ __forceinline__ void mma16816(float* c, const u32* a, u32 b0, u32 b1) {
    asm volatile(
        "mma.sync.aligned.m16n8k16.row.col.f32.bf16.bf16.f32 "
        "{%0,%1,%2,%3}, {%4,%5,%6,%7}, {%8,%9}, {%0,%1,%2,%3};"
        : "+f"(c[0]), "+f"(c[1]), "+f"(c[2]), "+f"(c[3])
        : "r"(a[0]), "r"(a[1]), "r"(a[2]), "r"(a[3]), "r"(b0), "r"(b1));
}
__device__ __forceinline__ void mbar_init(u32 mb, u32 c) {
    asm volatile("mbarrier.init.shared.b64 [%0], %1;" :: "r"(mb), "r"(c)
                 : "memory");
}
__device__ __forceinline__ void mbar_expect_tx(u32 mb, u32 tx) {
    asm volatile("mbarrier.arrive.expect_tx.shared.b64 _, [%0], %1;"
                 :: "r"(mb), "r"(tx) : "memory");
}
__device__ __forceinline__ void bulk_g2s(u32 dst, const void* src, u32 bytes,
                                         u32 mb) {
    asm volatile(
        "cp.async.bulk.shared::cta.global.mbarrier::complete_tx::bytes "
        "[%0], [%1], %2, [%3];"
        :: "r"(dst), "l"(src), "r"(bytes), "r"(mb) : "memory");
}
__device__ __forceinline__ void mbar_wait(u32 mb, u32 parity) {
    asm volatile(
        "{\n\t.reg .pred P;\n\t"
        "W%=:\n\t"
        "mbarrier.try_wait.parity.acquire.cta.shared::cta.b64 P, [%0], %1, 0x989680;\n\t"
        "@!P bra W%=;\n\t}"
        :: "r"(mb), "r"(parity) : "memory");
}

// ---------------- bf16 pack helpers (bf16x2 single-cvt path) ----------------
__device__ __forceinline__ u32 packbf2(float x0, float x1) {
    __nv_bfloat162 t = __floats2bfloat162_rn(x0, x1);   // .x=x0 (low), .y=x1
    return *reinterpret_cast<u32*>(&t);
}
__device__ __forceinline__ float2 unpbf2(u32 p) {
    __nv_bfloat162 t = *reinterpret_cast<__nv_bfloat162*>(&p);
    return __bfloat1622float2(t);
}
__device__ __forceinline__ float bf2f(unsigned short v) {
    return __bfloat162float(__ushort_as_bfloat16(v));
}
__device__ __forceinline__ float warpsum(float v) {
#pragma unroll
    for (int o = 16; o; o >>= 1) v += __shfl_xor_sync(0xffffffffu, v, o);
    return v;
}

// ---------------- prep: weights -> split, tile-packed image; zero g_cnt ----
__global__ void prep(const float* __restrict__ Wi, const float* __restrict__ Wb,
                     const float* __restrict__ Wo) {
    int idx = blockIdx.x * 256 + threadIdx.x;        // 245760 total
    if (idx < NG) g_cnt[idx] = 0u;
    const float* W; int k, n, N; long base;
    if (idx < 16384) {
        W = Wi; N = 256; k = idx >> 8; n = idx & 255; base = IMG_STEM;
    } else if (idx < 212992) {
        int e = idx - 16384; int b = e >> 16; e &= 65535;
        W = Wb + (size_t)b * 65536; N = 256; k = e >> 8; n = e & 255;
        base = IMG_BLK + (long)b * IMG_BLKSTR;
    } else {
        int e = idx - 212992;
        W = Wo; N = 128; k = e >> 7; n = e & 127; base = IMG_HEAD;
    }
    float w = W[(size_t)k * N + n];
    __nv_bfloat16 h = __float2bfloat16(w);
    __nv_bfloat16 l = __float2bfloat16(w - __bfloat162float(h));
    int kk = k & 15;
    long off = base + (long)(k >> 4) * ((long)N * 64)
             + (long)(n >> 4) * 512
             + (long)((((n >> 3) & 1) * 2 + (kk >> 3)) * 128)
             + (n & 7) * 16 + (kk & 7) * 2;
    *(__nv_bfloat16*)(g_wimg + off) = h;
    *(__nv_bfloat16*)(g_wimg + off + (long)N * 32) = l;
}

// ---------------- staged GEMM (bulk ring) ----------------
template<int N>   // 256 or 128
__device__ __forceinline__ void gemmA(
    u32 smb, const unsigned char* img, int nchunk,
    float (&acc)[2][8][4], int tid, int lane, int m0, int nq,
    int a_row, int a_kh, int (&ph)[2])
{
    constexpr int NH = N / 128;            // n16-pair groups per warp (2|1)
    constexpr u32 CB = (u32)N * 64;        // chunk bytes (2 planes)
    const int n16b = nq * (N / 64);        // first n16 index for this warp

    const u32 axh = smb + (u32)(m0 + a_row) * XA_RS + a_kh * 16;
    const u32 axl = axh + XA_PL;
    const u32 mb0 = smb + A_MB;

#pragma unroll
    for (int mt = 0; mt < 2; ++mt)
#pragma unroll
        for (int nt = 0; nt < 8; ++nt)
#pragma unroll
            for (int e = 0; e < 4; ++e) acc[mt][nt][e] = 0.f;

    __syncthreads();   // prior slot readers + plane writers done
    if (tid == 0) {
        mbar_expect_tx(mb0, CB);
        bulk_g2s(smb + A_RING, img, CB, mb0);
        mbar_expect_tx(mb0 + 8, CB);
        bulk_g2s(smb + A_RING + A_SLOTB, img + CB, CB, mb0 + 8);
    }

    for (int ch = 0; ch < nchunk; ++ch) {
        const int s = ch & 1;
        mbar_wait(mb0 + 8 * s, (u32)ph[s]);
        ph[s] ^= 1;
        const u32 slot = smb + A_RING + (u32)s * A_SLOTB;
        const u32 kb = (u32)ch * 32;       // 16 k-values = 32 B in x planes

        u32 ah0[4], ah1[4], al0[4], al1[4];
        ldsm4(ah0, axh + kb);
        ldsm4(ah1, axh + 16 * XA_RS + kb);
        ldsm4(al0, axl + kb);
        ldsm4(al1, axl + 16 * XA_RS + kb);
#pragma unroll
        for (int hf = 0; hf < NH; ++hf) {
            u32 bh[2][4], bl[2][4];
#pragma unroll
            for (int p = 0; p < 2; ++p) {
                const u32 wa = slot + (u32)(n16b + hf * 2 + p) * 512
                             + (u32)lane * 16;
                ldsm4(bh[p], wa);
                ldsm4(bl[p], wa + (u32)N * 32);
            }
            // term 1: Ahi * Bhi
#pragma unroll
            for (int p = 0; p < 2; ++p)
#pragma unroll
                for (int h = 0; h < 2; ++h) {
                    int nt = (hf * 2 + p) * 2 + h;
                    mma16816(acc[0][nt], ah0, bh[p][2*h], bh[p][2*h+1]);
                    mma16816(acc[1][nt], ah1, bh[p][2*h], bh[p][2*h+1]);
                }
            // term 2: Alo * Bhi
#pragma unroll
            for (int p = 0; p < 2; ++p)
#pragma unroll
                for (int h = 0; h < 2; ++h) {
                    int nt = (hf * 2 + p) * 2 + h;
                    mma16816(acc[0][nt], al0, bh[p][2*h], bh[p][2*h+1]);
                    mma16816(acc[1][nt], al1, bh[p][2*h], bh[p][2*h+1]);
                }
            // term 3: Ahi * Blo
#pragma unroll
            for (int p = 0; p < 2; ++p)
#pragma unroll
                for (int h = 0; h < 2; ++h) {
                    int nt = (hf * 2 + p) * 2 + h;
                    mma16816(acc[0][nt], ah0, bl[p][2*h], bl[p][2*h+1]);
                    mma16816(acc[1][nt], ah1, bl[p][2*h], bl[p][2*h+1]);
                }
        }
        if (ch + 2 < nchunk) {
            __syncthreads();   // all warps done reading slot s
            if (tid == 0) {
                mbar_expect_tx(mb0 + 8 * s, CB);
                bulk_g2s(slot, img + (size_t)(ch + 2) * CB, CB, mb0 + 8 * s);
            }
        }
    }
}

// ---------------- mlp (+ fused pool on second finisher) ----------------
__global__ void __launch_bounds__(TPA, 2)
mlp(const float* __restrict__ H,
    const float* __restrict__ b_in, const float* __restrict__ g_in,
    const float* __restrict__ be_in,
    const float* __restrict__ bb, const float* __restrict__ gb,
    const float* __restrict__ betab,
    const float* __restrict__ b_out, const float* __restrict__ g_out,
    const float* __restrict__ be_out,
    float* __restrict__ out)
{
    extern __shared__ __align__(128) unsigned char smc[];
    __shared__ unsigned int s_flag;
    const u32 smb = s2u(smc);
    const int tid = threadIdx.x, lane = tid & 31, w = tid >> 5;
    const int qr = lane >> 2, qc = lane & 3;
    const int m0 = (w & 1) * 32, nq = w >> 1;
    const int grp = lane >> 3, ri = lane & 7;
    const int a_row = (grp & 1) * 8 + ri, a_kh = grp >> 1;
    const int g = blockIdx.x >> 1, mh = blockIdx.x & 1;

    float2* part = (float2*)(smc + A_PART);
    int ph[2] = {0, 0};

    if (tid == 0) {
        mbar_init(smb + A_MB, 1);
        mbar_init(smb + A_MB + 8, 1);
    }

    // ---- load H (64 rows, node base mh*64) -> hi/lo planes ----
    {
        const int row = tid >> 2, c4 = tid & 3;
        const float4* hs = (const float4*)(H + (size_t)g * NODES * IND
                                           + (size_t)(mh * 64 + row) * IND
                                           + c4 * 16);
        const u32 off = (u32)row * XA_RS + (u32)c4 * 32;
#pragma unroll
        for (int q = 0; q < 4; ++q) {
            float4 v = hs[q];
            u32 h0 = packbf2(v.x, v.y), h1 = packbf2(v.z, v.w);
            float2 f0 = unpbf2(h0), f1 = unpbf2(h1);
            u32 l0 = packbf2(v.x - f0.x, v.y - f0.y);
            u32 l1 = packbf2(v.z - f1.x, v.w - f1.y);
            *(u32*)(smc + off + q * 8)             = h0;
            *(u32*)(smc + off + q * 8 + 4)         = h1;
            *(u32*)(smc + XA_PL + off + q * 8)     = l0;
            *(u32*)(smc + XA_PL + off + q * 8 + 4) = l1;
        }
    }

    float acc[2][8][4];

    // ---- LN(+relu,+residual) epilogue N=256, rewrites x planes ----
    auto ep256 = [&](const float* bias, const float* gam, const float* bet,
                     bool res) {
        const int n0 = nq * 64;
        float s1[4] = {0.f, 0.f, 0.f, 0.f}, s2[4] = {0.f, 0.f, 0.f, 0.f};
#pragma unroll
        for (int nt = 0; nt < 8; ++nt) {
            float2 bp = *(const float2*)&bias[n0 + nt * 8 + qc * 2];
#pragma unroll
            for (int mt = 0; mt < 2; ++mt) {
                float* c = acc[mt][nt];
                c[0] += bp.x; c[1] += bp.y; c[2] += bp.x; c[3] += bp.y;
                s1[mt*2]   += c[0] + c[1];
                s2[mt*2]    = fmaf(c[0], c[0], fmaf(c[1], c[1], s2[mt*2]));
                s1[mt*2+1] += c[2] + c[3];
                s2[mt*2+1]  = fmaf(c[2], c[2], fmaf(c[3], c[3], s2[mt*2+1]));
            }
        }
#pragma unroll
        for (int r = 0; r < 4; ++r) {
            s1[r] += __shfl_xor_sync(0xffffffffu, s1[r], 1);
            s1[r] += __shfl_xor_sync(0xffffffffu, s1[r], 2);
            s2[r] += __shfl_xor_sync(0xffffffffu, s2[r], 1);
            s2[r] += __shfl_xor_sync(0xffffffffu, s2[r], 2);
        }
        __syncthreads();
        if (qc == 0) {
#pragma unroll
            for (int r = 0; r < 4; ++r) {
                int row = m0 + (r >> 1) * 16 + (r & 1) * 8 + qr;
                part[row * 4 + nq] = make_float2(s1[r], s2[r]);
            }
        }
        __syncthreads();
        float mu[4], rs[4];
#pragma unroll
        for (int r = 0; r < 4; ++r) {
            int row = m0 + (r >> 1) * 16 + (r & 1) * 8 + qr;
            float4 p0 = *(float4*)&part[row * 4];
            float4 p1 = *(float4*)&part[row * 4 + 2];
            float S1 = p0.x + p0.z + p1.x + p1.z;
            float S2 = p0.y + p0.w + p1.y + p1.w;
            float m_ = S1 * (1.f / 256.f);
            mu[r] = m_;
            rs[r] = rsqrtf(fmaf(-m_, m_, S2 * (1.f / 256.f)) + 1e-5f);
        }
        __syncthreads();
#pragma unroll
        for (int nt = 0; nt < 8; ++nt) {
            int col = n0 + nt * 8 + qc * 2;
            float2 gg = *(const float2*)&gam[col];
            float2 ee = *(const float2*)&bet[col];
#pragma unroll
            for (int mt = 0; mt < 2; ++mt)
#pragma unroll
                for (int h = 0; h < 2; ++h) {
                    int r4 = mt * 2 + h;
                    int row = m0 + mt * 16 + h * 8 + qr;
                    float v0 = acc[mt][nt][2 * h], v1 = acc[mt][nt][2 * h + 1];
                    float y0 = fmaxf(fmaf((v0 - mu[r4]) * rs[r4], gg.x, ee.x), 0.f);
                    float y1 = fmaxf(fmaf((v1 - mu[r4]) * rs[r4], gg.y, ee.y), 0.f);
                    u32 off = (u32)row * XA_RS + (u32)col * 2;
                    if (res) {
                        float2 oh = unpbf2(*(u32*)(smc + off));
                        float2 ol = unpbf2(*(u32*)(smc + XA_PL + off));
                        y0 += oh.x + ol.x;
                        y1 += oh.y + ol.y;
                    }
                    u32 hh = packbf2(y0, y1);
                    float2 hf = unpbf2(hh);
                    u32 ll = packbf2(y0 - hf.x, y1 - hf.y);
                    *(u32*)(smc + off)         = hh;
                    *(u32*)(smc + XA_PL + off) = ll;
                }
        }
    };

    // ---- pipeline ----
    gemmA<256>(smb, g_wimg + IMG_STEM, 4, acc, tid, lane, m0, nq,
               a_row, a_kh, ph);
    ep256(b_in, g_in, be_in, false);
    for (int b = 0; b < NBLK; ++b) {
        gemmA<256>(smb, g_wimg + IMG_BLK + (size_t)b * IMG_BLKSTR, 16,
                   acc, tid, lane, m0, nq, a_row, a_kh, ph);
        ep256(bb + b * HID, gb + b * HID, betab + b * HID, true);
    }
    gemmA<128>(smb, g_wimg + IMG_HEAD, 16, acc, tid, lane, m0, nq,
               a_row, a_kh, ph);

    // ---- head epilogue: z = LN(.), write to g_z ----
    {
        const int n0 = nq * 32;
        float s1[4] = {0.f, 0.f, 0.f, 0.f}, s2[4] = {0.f, 0.f, 0.f, 0.f};
#pragma unroll
        for (int nt = 0; nt < 4; ++nt) {
            float2 bp = *(const float2*)&b_out[n0 + nt * 8 + qc * 2];
#pragma unroll
            for (int mt = 0; mt < 2; ++mt) {
                float* c = acc[mt][nt];
                c[0] += bp.x; c[1] += bp.y; c[2] += bp.x; c[3] += bp.y;
                s1[mt*2]   += c[0] + c[1];
                s2[mt*2]    = fmaf(c[0], c[0], fmaf(c[1], c[1], s2[mt*2]));
                s1[mt*2+1] += c[2] + c[3];
                s2[mt*2+1]  = fmaf(c[2], c[2], fmaf(c[3], c[3], s2[mt*2+1]));
            }
        }
#pragma unroll
        for (int r = 0; r < 4; ++r) {
            s1[r] += __shfl_xor_sync(0xffffffffu, s1[r], 1);
            s1[r] += __shfl_xor_sync(0xffffffffu, s1[r], 2);
            s2[r] += __shfl_xor_sync(0xffffffffu, s2[r], 1);
            s2[r] += __shfl_xor_sync(0xffffffffu, s2[r], 2);
        }
        __syncthreads();
        if (qc == 0) {
#pragma unroll
            for (int r = 0; r < 4; ++r) {
                int row = m0 + (r >> 1) * 16 + (r & 1) * 8 + qr;
                part[row * 4 + nq] = make_float2(s1[r], s2[r]);
            }
        }
        __syncthreads();
        float mu[4], rs[4];
#pragma unroll
        for (int r = 0; r < 4; ++r) {
            int row = m0 + (r >> 1) * 16 + (r & 1) * 8 + qr;
            float4 p0 = *(float4*)&part[row * 4];
            float4 p1 = *(float4*)&part[row * 4 + 2];
            float S1 = p0.x + p0.z + p1.x + p1.z;
            float S2 = p0.y + p0.w + p1.y + p1.w;
            float m_ = S1 * (1.f / 128.f);
            mu[r] = m_;
            rs[r] = rsqrtf(fmaf(-m_, m_, S2 * (1.f / 128.f)) + 1e-5f);
        }
        float* zbase = g_z + (size_t)g * (NODES * OUTD);
#pragma unroll
        for (int nt = 0; nt < 4; ++nt) {
            int col = n0 + nt * 8 + qc * 2;
            float2 gg = *(const float2*)&g_out[col];
            float2 ee = *(const float2*)&be_out[col];
#pragma unroll
            for (int mt = 0; mt < 2; ++mt)
#pragma unroll
                for (int h = 0; h < 2; ++h) {
                    int r4 = mt * 2 + h;
                    int row = m0 + mt * 16 + h * 8 + qr;
                    float z0 = fmaf((acc[mt][nt][2*h]   - mu[r4]) * rs[r4], gg.x, ee.x);
                    float z1 = fmaf((acc[mt][nt][2*h+1] - mu[r4]) * rs[r4], gg.y, ee.y);
                    *(float2*)(zbase + (size_t)(mh * 64 + row) * OUTD + col) =
                        make_float2(z0, z1);
                }
        }
    }

    // ---- handoff: second finisher of the graph pair runs the pool ----
    __syncthreads();
    if (tid == 0) {
        __threadfence();                       // publish this CTA's z
        unsigned int old = atomicAdd(&g_cnt[g], 1u);
        s_flag = old;                          // 1 -> we are second
    }
    __syncthreads();
    if (s_flag != 1u) return;
    __threadfence();                           // acquire peer CTA's z

    // ================== fused pool (Gram + softmax + weighted sum) =========
    {
        const int m0p = (w & 3) * 32, nh = w >> 2;
        const int n0p = nh * 64;

        float* sqf   = (float*)(smc + B_SQ);
        float* partf = (float*)(smc + B_PART);
        float* ssm   = (float*)(smc + B_SSM);
        float* wsm   = (float*)(smc + B_WSM);
        float* vpart = (float*)(smc + B_VP);

        // ---- load z, convert to hi/lo planes, row norms ----
        const float* zbase = g_z + (size_t)g * (NODES * OUTD);
#pragma unroll 1
        for (int j = 0; j < 16; ++j) {
            int r = w * 16 + j;
            float4 v = ((const float4*)(zbase + (size_t)r * OUTD))[lane];
            u32 h0 = packbf2(v.x, v.y), h1 = packbf2(v.z, v.w);
            float2 f0 = unpbf2(h0), f1 = unpbf2(h1);
            u32 l0 = packbf2(v.x - f0.x, v.y - f0.y);
            u32 l1 = packbf2(v.z - f1.x, v.w - f1.y);
            u32 off = (u32)r * ZB_RS + (u32)lane * 8;
            *(u32*)(smc + off)             = h0;
            *(u32*)(smc + off + 4)         = h1;
            *(u32*)(smc + ZB_PL + off)     = l0;
            *(u32*)(smc + ZB_PL + off + 4) = l1;
            float sq = fmaf(v.x, v.x, fmaf(v.y, v.y, fmaf(v.z, v.z, v.w * v.w)));
            sq = warpsum(sq);
            if (lane == 0) sqf[r] = sq;
        }
        __syncthreads();

        // ---- Gram via bf16x3 mma (warp tile 32x64) ----
        float acc2[2][8][4];
#pragma unroll
        for (int mt = 0; mt < 2; ++mt)
#pragma unroll
            for (int nt = 0; nt < 8; ++nt)
#pragma unroll
                for (int e = 0; e < 4; ++e) acc2[mt][nt][e] = 0.f;

        const int b_n = (grp >> 1) * 8 + ri, b_kh = grp & 1;
        const u32 azh = smb + (u32)(m0p + a_row) * ZB_RS + a_kh * 16;
        const u32 azl = azh + ZB_PL;
        const u32 bzh = smb + (u32)(n0p + b_n) * ZB_RS + b_kh * 16;
        const u32 bzl = bzh + ZB_PL;
#pragma unroll
        for (int ks = 0; ks < 8; ++ks) {
            const u32 kb = (u32)ks * 32;
            u32 ah0[4], ah1[4], al0[4], al1[4];
            ldsm4(ah0, azh + kb);
            ldsm4(ah1, azh + 16 * ZB_RS + kb);
            ldsm4(al0, azl + kb);
            ldsm4(al1, azl + 16 * ZB_RS + kb);
#pragma unroll
            for (int hf = 0; hf < 2; ++hf) {
                u32 bh[2][4], bl[2][4];
#pragma unroll
                for (int p = 0; p < 2; ++p) {
                    const u32 wa = (u32)(hf * 2 + p) * 16 * ZB_RS + kb;
                    ldsm4(bh[p], bzh + wa);
                    ldsm4(bl[p], bzl + wa);
                }
#pragma unroll
                for (int p = 0; p < 2; ++p)
#pragma unroll
                    for (int h = 0; h < 2; ++h) {
                        int nt = (hf * 2 + p) * 2 + h;
                        mma16816(acc2[0][nt], ah0, bh[p][2*h], bh[p][2*h+1]);
                        mma16816(acc2[1][nt], ah1, bh[p][2*h], bh[p][2*h+1]);
                    }
#pragma unroll
                for (int p = 0; p < 2; ++p)
#pragma unroll
                    for (int h = 0; h < 2; ++h) {
                        int nt = (hf * 2 + p) * 2 + h;
                        mma16816(acc2[0][nt], al0, bh[p][2*h], bh[p][2*h+1]);
                        mma16816(acc2[1][nt], al1, bh[p][2*h], bh[p][2*h+1]);
                    }
#pragma unroll
                for (int p = 0; p < 2; ++p)
#pragma unroll
                    for (int h = 0; h < 2; ++h) {
                        int nt = (hf * 2 + p) * 2 + h;
                        mma16816(acc2[0][nt], ah0, bl[p][2*h], bl[p][2*h+1]);
                        mma16816(acc2[1][nt], ah1, bl[p][2*h], bl[p][2*h+1]);
                    }
            }
        }

        // ---- distances -> per-row sums ----
        float sa[4] = {0.f, 0.f, 0.f, 0.f};
#pragma unroll
        for (int nt = 0; nt < 8; ++nt) {
            int col = n0p + nt * 8 + qc * 2;
            float sc0 = sqf[col], sc1 = sqf[col + 1];
#pragma unroll
            for (int mt = 0; mt < 2; ++mt)
#pragma unroll
                for (int h = 0; h < 2; ++h) {
                    int r4 = mt * 2 + h;
                    int row = m0p + mt * 16 + h * 8 + qr;
                    float sr = sqf[row];
                    float d0 = sr + sc0 - 2.f * acc2[mt][nt][2 * h];
                    float d1 = sr + sc1 - 2.f * acc2[mt][nt][2 * h + 1];
                    float t0 = (col == row) ? 1e-6f
                               : sqrtf(fmaxf(d0, 0.f) + 1e-12f);
                    float t1 = (col + 1 == row) ? 1e-6f
                               : sqrtf(fmaxf(d1, 0.f) + 1e-12f);
                    sa[r4] += t0 + t1;
                }
        }
#pragma unroll
        for (int r = 0; r < 4; ++r) {
            sa[r] += __shfl_xor_sync(0xffffffffu, sa[r], 1);
            sa[r] += __shfl_xor_sync(0xffffffffu, sa[r], 2);
        }
        if (qc == 0) {
#pragma unroll
            for (int r = 0; r < 4; ++r) {
                int row = m0p + (r >> 1) * 16 + (r & 1) * 8 + qr;
                partf[row * 2 + nh] = sa[r];
            }
        }
        __syncthreads();
        if (tid < NODES)
            ssm[tid] = (partf[tid * 2] + partf[tid * 2 + 1]) * (1.f / 128.f);
        __syncthreads();

        // ---- softmax (warp 0) ----
        if (w == 0) {
            const float sc = 1.f / 0.25f;
            float sv[4], mx = -1e30f;
#pragma unroll
            for (int q = 0; q < 4; ++q) {
                sv[q] = ssm[lane + 32 * q] * sc;
                mx = fmaxf(mx, sv[q]);
            }
#pragma unroll
            for (int o = 16; o; o >>= 1)
                mx = fmaxf(mx, __shfl_xor_sync(0xffffffffu, mx, o));
            float e[4], se = 0.f;
#pragma unroll
            for (int q = 0; q < 4; ++q) { e[q] = expf(sv[q] - mx); se += e[q]; }
#pragma unroll
            for (int o = 16; o; o >>= 1)
                se += __shfl_xor_sync(0xffffffffu, se, o);
            float inv = 1.f / se;
#pragma unroll
            for (int q = 0; q < 4; ++q) {
                float ww = e[q] * inv;
                int i = lane + 32 * q;
                wsm[i] = ww;
                out[(size_t)NG * OUTD + (size_t)g * NODES + i] = ww;
            }
        }
        __syncthreads();

        // ---- pool: v[d] = sum_i w_i * (hi+lo)[i][d], 2 i-halves ----
        {
            int d = tid & 127, hseg = tid >> 7;
            float a = 0.f;
#pragma unroll 4
            for (int i = hseg * 64; i < hseg * 64 + 64; ++i) {
                u32 off = (u32)i * ZB_RS + (u32)d * 2;
                float zv = bf2f(*(unsigned short*)(smc + off))
                         + bf2f(*(unsigned short*)(smc + ZB_PL + off));
                a = fmaf(wsm[i], zv, a);
            }
            vpart[hseg * 128 + d] = a;
        }
        __syncthreads();
        if (tid < OUTD)
            out[(size_t)g * OUTD + tid] = vpart[tid] + vpart[128 + tid];
    }
}

}  // namespace lb

extern "C" void kernel_launch(void* const* d_in, const int* in_sizes, int n_in,
                              void* d_out, int out_size)
{
    (void)in_sizes; (void)n_in; (void)out_size;
    const float* H     = (const float*)d_in[0];
    const float* W_in  = (const float*)d_in[2];
    const float* b_in  = (const float*)d_in[3];
    const float* g_in  = (const float*)d_in[4];
    const float* be_in = (const float*)d_in[5];
    const float* Wb    = (const float*)d_in[6];
    const float* bb    = (const float*)d_in[7];
    const float* gb    = (const float*)d_in[8];
    const float* betab = (const float*)d_in[9];
    const float* W_out = (const float*)d_in[10];
    const float* b_out = (const float*)d_in[11];
    const float* g_out = (const float*)d_in[12];
    const float* be_out= (const float*)d_in[13];
    float* out = (float*)d_out;

    lb::prep<<<960, 256>>>(W_in, Wb, W_out);

    cudaFuncSetAttribute(lb::mlp,
                         cudaFuncAttributeMaxDynamicSharedMemorySize,
                         lb::SMEM_A);

    lb::mlp<<<2 * lb::NG, lb::TPA, lb::SMEM_A>>>(
        H, b_in, g_in, be_in, bb, gb, betab, b_out, g_out, be_out, out);
}

// round 15
// speedup vs baseline: 1.0717x; 1.0172x over previous
#include <cuda_runtime.h>
#include <cuda_bf16.h>
#include <cstdint>

// ============================================================================
// LocalBranch round 15: R14 base (521us) with the weight-ring's per-chunk
// __syncthreads replaced by producer/consumer mbarriers (empty-barrier with
// one arrival per warp; only tid0 waits before refilling). Consumers never
// block at refill points; 68 CTA-wide barriers removed per CTA.
//  mlp: 2048 CTAs x 256 thr, 64 nodes each, bf16x3 mma.sync, tile-packed k16
//  chunks via 2-slot cp.async.bulk ring; z -> g_z; 2nd finisher pools inline.
// ============================================================================

namespace lb {

using u32 = uint32_t;

constexpr int NODES = 128, IND = 64, HID = 256, OUTD = 128, NBLK = 3, NG = 1024;

// ---- mlp smem ----
constexpr int TPA   = 256;
constexpr int XA_RS = 528;               // x-plane row stride (bytes)
constexpr int XA_PL = 64 * XA_RS;        // 33792 per plane (64 rows)
constexpr int A_RING = 2 * XA_PL;        // 67584
constexpr int A_SLOTB = 16384;           // max chunk bytes (N=256)
constexpr int A_PART = A_RING + 2 * A_SLOTB;   // 100352: float2[64*4]
constexpr int A_MB   = A_PART + 2048;    // 102400: 4 mbarriers (fb0 fb1 eb0 eb1)
constexpr int SMEM_A = A_MB + 48;        // 102448 (x2 = 204896 <= 228KB)

// ---- pool-phase smem overlay ----
constexpr int ZB_RS = 272;               // z-plane row stride (bytes)
constexpr int ZB_PL = 128 * ZB_RS;       // 34816 per plane
constexpr int B_SQ   = 2 * ZB_PL;        // 69632: float[128]
constexpr int B_PART = B_SQ + 512;       // float[256]
constexpr int B_SSM  = B_PART + 1024;    // float[128]
constexpr int B_WSM  = B_SSM + 512;      // float[128]
constexpr int B_VP   = B_WSM + 512;      // float[256] (ends 73216 < SMEM_A)

// ---- weight image: k16 chunks of ldsm-ready 128B tiles (see prep) ----
constexpr long IMG_STEM   = 0;                    // 4 chunks x 16384
constexpr long IMG_BLK    = 65536;                // 3 x 16 x 16384
constexpr long IMG_BLKSTR = 262144;
constexpr long IMG_HEAD   = 851968;               // 16 x 8192
__device__ __align__(128) unsigned char g_wimg[983040];
__device__ float g_z[(size_t)NG * NODES * OUTD];  // 64 MB scratch
__device__ unsigned int g_cnt[NG];                // per-graph finish counter

// ---------------- PTX helpers ----------------
__device__ __forceinline__ u32 s2u(const void* p) {
    u32 a;
    asm("{ .reg .u64 t; cvta.to.shared.u64 t, %1; cvt.u32.u64 %0, t; }"
        : "=r"(a) : "l"(p));
    return a;
}
__device__ __forceinline__ void ldsm4(u32* r, u32 addr) {
    asm volatile("ldmatrix.sync.aligned.m8n8.x4.shared.b16 {%0,%1,%2,%3}, [%4];"
                 : "=r"(r[0]), "=r"(r[1]), "=r"(r[2]), "=r"(r[3]) : "r"(addr));
}
__device__ __forceinline__ void mma16816(float* c, const u32* a, u32 b0, u32 b1) {
    asm volatile(
        "mma.sync.aligned.m16n8k16.row.col.f32.bf16.bf16.f32 "
        "{%0,%1,%2,%3}, {%4,%5,%6,%7}, {%8,%9}, {%0,%1,%2,%3};"
        : "+f"(c[0]), "+f"(c[1]), "+f"(c[2]), "+f"(c[3])
        : "r"(a[0]), "r"(a[1]), "r"(a[2]), "r"(a[3]), "r"(b0), "r"(b1));
}
__device__ __forceinline__ void mbar_init(u32 mb, u32 c) {
    asm volatile("mbarrier.init.shared.b64 [%0], %1;" :: "r"(mb), "r"(c)
                 : "memory");
}
__device__ __forceinline__ void mbar_arrive(u32 mb) {
    asm volatile("mbarrier.arrive.shared.b64 _, [%0];" :: "r"(mb) : "memory");
}
__device__ __forceinline__ void mbar_expect_tx(u32 mb, u32 tx) {
    asm volatile("mbarrier.arrive.expect_tx.shared.b64 _, [%0], %1;"
                 :: "r"(mb), "r"(tx) : "memory");
}
__device__ __forceinline__ void bulk_g2s(u32 dst, const void* src, u32 bytes,
                                         u32 mb) {
    asm volatile(
        "cp.async.bulk.shared::cta.global.mbarrier::complete_tx::bytes "
        "[%0], [%1], %2, [%3];"
        :: "r"(dst), "l"(src), "r"(bytes), "r"(mb) : "memory");
}
__device__ __forceinline__ void mbar_wait(u32 mb, u32 parity) {
    asm volatile(
        "{\n\t.reg .pred P;\n\t"
        "W%=:\n\t"
        "mbarrier.try_wait.parity.acquire.cta.shared::cta.b64 P, [%0], %1, 0x989680;\n\t"
        "@!P bra W%=;\n\t}"
        :: "r"(mb), "r"(parity) : "memory");
}

// ---------------- bf16 pack helpers (bf16x2 single-cvt path) ----------------
__device__ __forceinline__ u32 packbf2(float x0, float x1) {
    __nv_bfloat162 t = __floats2bfloat162_rn(x0, x1);
    return *reinterpret_cast<u32*>(&t);
}
__device__ __forceinline__ float2 unpbf2(u32 p) {
    __nv_bfloat162 t = *reinterpret_cast<__nv_bfloat162*>(&p);
    return __bfloat1622float2(t);
}
__device__ __forceinline__ float bf2f(unsigned short v) {
    return __bfloat162float(__ushort_as_bfloat16(v));
}
__device__ __forceinline__ float warpsum(float v) {
#pragma unroll
    for (int o = 16; o; o >>= 1) v += __shfl_xor_sync(0xffffffffu, v, o);
    return v;
}

// ---------------- prep: weights -> split, tile-packed image; zero g_cnt ----
__global__ void prep(const float* __restrict__ Wi, const float* __restrict__ Wb,
                     const float* __restrict__ Wo) {
    int idx = blockIdx.x * 256 + threadIdx.x;        // 245760 total
    if (idx < NG) g_cnt[idx] = 0u;
    const float* W; int k, n, N; long base;
    if (idx < 16384) {
        W = Wi; N = 256; k = idx >> 8; n = idx & 255; base = IMG_STEM;
    } else if (idx < 212992) {
        int e = idx - 16384; int b = e >> 16; e &= 65535;
        W = Wb + (size_t)b * 65536; N = 256; k = e >> 8; n = e & 255;
        base = IMG_BLK + (long)b * IMG_BLKSTR;
    } else {
        int e = idx - 212992;
        W = Wo; N = 128; k = e >> 7; n = e & 127; base = IMG_HEAD;
    }
    float w = W[(size_t)k * N + n];
    __nv_bfloat16 h = __float2bfloat16(w);
    __nv_bfloat16 l = __float2bfloat16(w - __bfloat162float(h));
    int kk = k & 15;
    long off = base + (long)(k >> 4) * ((long)N * 64)
             + (long)(n >> 4) * 512
             + (long)((((n >> 3) & 1) * 2 + (kk >> 3)) * 128)
             + (n & 7) * 16 + (kk & 7) * 2;
    *(__nv_bfloat16*)(g_wimg + off) = h;
    *(__nv_bfloat16*)(g_wimg + off + (long)N * 32) = l;
}

// ---------------- staged GEMM: bulk ring with producer/consumer mbarriers ---
// fb[s] = full barrier (flipped by bulk complete_tx), eb[s] = empty barrier
// (8 arrivals, lane0 of each warp, after the chunk's mmas). Only tid0 waits
// on eb before refilling; consumers never hit a CTA-wide barrier per chunk.
template<int N>   // 256 or 128
__device__ __forceinline__ void gemmA(
    u32 smb, const unsigned char* img, int nchunk, bool first,
    float (&acc)[2][8][4], int tid, int lane, int m0, int nq,
    int a_row, int a_kh, int (&ph)[2], int (&pe)[2])
{
    constexpr int NH = N / 128;            // n16-pair groups per warp (2|1)
    constexpr u32 CB = (u32)N * 64;        // chunk bytes (2 planes)
    const int n16b = nq * (N / 64);        // first n16 index for this warp

    const u32 axh = smb + (u32)(m0 + a_row) * XA_RS + a_kh * 16;
    const u32 axl = axh + XA_PL;
    const u32 fb0 = smb + A_MB,      fb1 = smb + A_MB + 8;
    const u32 eb0 = smb + A_MB + 16, eb1 = smb + A_MB + 24;

#pragma unroll
    for (int mt = 0; mt < 2; ++mt)
#pragma unroll
        for (int nt = 0; nt < 8; ++nt)
#pragma unroll
            for (int e = 0; e < 4; ++e) acc[mt][nt][e] = 0.f;

    __syncthreads();   // plane writes (and, for !first, prior-GEMM arrivals)
    if (tid == 0) {
        if (!first) { mbar_wait(eb0, (u32)pe[0]); pe[0] ^= 1; }   // immediate
        mbar_expect_tx(fb0, CB);
        bulk_g2s(smb + A_RING, img, CB, fb0);
        if (!first) { mbar_wait(eb1, (u32)pe[1]); pe[1] ^= 1; }   // immediate
        mbar_expect_tx(fb1, CB);
        bulk_g2s(smb + A_RING + A_SLOTB, img + CB, CB, fb1);
    }

    for (int ch = 0; ch < nchunk; ++ch) {
        const int s = ch & 1;
        const u32 fb = s ? fb1 : fb0;
        const u32 eb = s ? eb1 : eb0;
        mbar_wait(fb, (u32)ph[s]);
        ph[s] ^= 1;
        const u32 slot = smb + A_RING + (u32)s * A_SLOTB;
        const u32 kb = (u32)ch * 32;       // 16 k-values = 32 B in x planes

        u32 ah0[4], ah1[4], al0[4], al1[4];
        ldsm4(ah0, axh + kb);
        ldsm4(ah1, axh + 16 * XA_RS + kb);
        ldsm4(al0, axl + kb);
        ldsm4(al1, axl + 16 * XA_RS + kb);
#pragma unroll
        for (int hf = 0; hf < NH; ++hf) {
            u32 bh[2][4], bl[2][4];
#pragma unroll
            for (int p = 0; p < 2; ++p) {
                const u32 wa = slot + (u32)(n16b + hf * 2 + p) * 512
                             + (u32)lane * 16;
                ldsm4(bh[p], wa);
                ldsm4(bl[p], wa + (u32)N * 32);
            }
            // term 1: Ahi * Bhi
#pragma unroll
            for (int p = 0; p < 2; ++p)
#pragma unroll
                for (int h = 0; h < 2; ++h) {
                    int nt = (hf * 2 + p) * 2 + h;
                    mma16816(acc[0][nt], ah0, bh[p][2*h], bh[p][2*h+1]);
                    mma16816(acc[1][nt], ah1, bh[p][2*h], bh[p][2*h+1]);
                }
            // term 2: Alo * Bhi
#pragma unroll
            for (int p = 0; p < 2; ++p)
#pragma unroll
                for (int h = 0; h < 2; ++h) {
                    int nt = (hf * 2 + p) * 2 + h;
                    mma16816(acc[0][nt], al0, bh[p][2*h], bh[p][2*h+1]);
                    mma16816(acc[1][nt], al1, bh[p][2*h], bh[p][2*h+1]);
                }
            // term 3: Ahi * Blo
#pragma unroll
            for (int p = 0; p < 2; ++p)
#pragma unroll
                for (int h = 0; h < 2; ++h) {
                    int nt = (hf * 2 + p) * 2 + h;
                    mma16816(acc[0][nt], ah0, bl[p][2*h], bl[p][2*h+1]);
                    mma16816(acc[1][nt], ah1, bl[p][2*h], bl[p][2*h+1]);
                }
        }
        // this warp is done with slot s (mma issue implies ldsm data consumed)
        if (lane == 0) mbar_arrive(eb);
        // producer: refill slot s with chunk ch+2 once all 8 warps arrived
        if (ch + 2 < nchunk && tid == 0) {
            mbar_wait(eb, (u32)pe[s]);
            pe[s] ^= 1;
            mbar_expect_tx(fb, CB);
            bulk_g2s(slot, img + (size_t)(ch + 2) * CB, CB, fb);
        }
    }
}

// ---------------- mlp (+ fused pool on second finisher) ----------------
__global__ void __launch_bounds__(TPA, 2)
mlp(const float* __restrict__ H,
    const float* __restrict__ b_in, const float* __restrict__ g_in,
    const float* __restrict__ be_in,
    const float* __restrict__ bb, const float* __restrict__ gb,
    const float* __restrict__ betab,
    const float* __restrict__ b_out, const float* __restrict__ g_out,
    const float* __restrict__ be_out,
    float* __restrict__ out)
{
    extern __shared__ __align__(128) unsigned char smc[];
    __shared__ unsigned int s_flag;
    const u32 smb = s2u(smc);
    const int tid = threadIdx.x, lane = tid & 31, w = tid >> 5;
    const int qr = lane >> 2, qc = lane & 3;
    const int m0 = (w & 1) * 32, nq = w >> 1;
    const int grp = lane >> 3, ri = lane & 7;
    const int a_row = (grp & 1) * 8 + ri, a_kh = grp >> 1;
    const int g = blockIdx.x >> 1, mh = blockIdx.x & 1;

    float2* part = (float2*)(smc + A_PART);
    int ph[2] = {0, 0};   // full-barrier phases
    int pe[2] = {0, 0};   // empty-barrier phases (tid0 bookkeeping)

    if (tid == 0) {
        mbar_init(smb + A_MB, 1);        // fb0
        mbar_init(smb + A_MB + 8, 1);    // fb1
        mbar_init(smb + A_MB + 16, 8);   // eb0 (one arrival per warp)
        mbar_init(smb + A_MB + 24, 8);   // eb1
    }

    // ---- load H (64 rows, node base mh*64) -> hi/lo planes ----
    {
        const int row = tid >> 2, c4 = tid & 3;
        const float4* hs = (const float4*)(H + (size_t)g * NODES * IND
                                           + (size_t)(mh * 64 + row) * IND
                                           + c4 * 16);
        const u32 off = (u32)row * XA_RS + (u32)c4 * 32;
#pragma unroll
        for (int q = 0; q < 4; ++q) {
            float4 v = hs[q];
            u32 h0 = packbf2(v.x, v.y), h1 = packbf2(v.z, v.w);
            float2 f0 = unpbf2(h0), f1 = unpbf2(h1);
            u32 l0 = packbf2(v.x - f0.x, v.y - f0.y);
            u32 l1 = packbf2(v.z - f1.x, v.w - f1.y);
            *(u32*)(smc + off + q * 8)             = h0;
            *(u32*)(smc + off + q * 8 + 4)         = h1;
            *(u32*)(smc + XA_PL + off + q * 8)     = l0;
            *(u32*)(smc + XA_PL + off + q * 8 + 4) = l1;
        }
    }

    float acc[2][8][4];

    // ---- LN(+relu,+residual) epilogue N=256, rewrites x planes ----
    auto ep256 = [&](const float* bias, const float* gam, const float* bet,
                     bool res) {
        const int n0 = nq * 64;
        float s1[4] = {0.f, 0.f, 0.f, 0.f}, s2[4] = {0.f, 0.f, 0.f, 0.f};
#pragma unroll
        for (int nt = 0; nt < 8; ++nt) {
            float2 bp = *(const float2*)&bias[n0 + nt * 8 + qc * 2];
#pragma unroll
            for (int mt = 0; mt < 2; ++mt) {
                float* c = acc[mt][nt];
                c[0] += bp.x; c[1] += bp.y; c[2] += bp.x; c[3] += bp.y;
                s1[mt*2]   += c[0] + c[1];
                s2[mt*2]    = fmaf(c[0], c[0], fmaf(c[1], c[1], s2[mt*2]));
                s1[mt*2+1] += c[2] + c[3];
                s2[mt*2+1]  = fmaf(c[2], c[2], fmaf(c[3], c[3], s2[mt*2+1]));
            }
        }
#pragma unroll
        for (int r = 0; r < 4; ++r) {
            s1[r] += __shfl_xor_sync(0xffffffffu, s1[r], 1);
            s1[r] += __shfl_xor_sync(0xffffffffu, s1[r], 2);
            s2[r] += __shfl_xor_sync(0xffffffffu, s2[r], 1);
            s2[r] += __shfl_xor_sync(0xffffffffu, s2[r], 2);
        }
        __syncthreads();   // all warps out of mma/ldsm before part+plane reuse
        if (qc == 0) {
#pragma unroll
            for (int r = 0; r < 4; ++r) {
                int row = m0 + (r >> 1) * 16 + (r & 1) * 8 + qr;
                part[row * 4 + nq] = make_float2(s1[r], s2[r]);
            }
        }
        __syncthreads();
        float mu[4], rs[4];
#pragma unroll
        for (int r = 0; r < 4; ++r) {
            int row = m0 + (r >> 1) * 16 + (r & 1) * 8 + qr;
            float4 p0 = *(float4*)&part[row * 4];
            float4 p1 = *(float4*)&part[row * 4 + 2];
            float S1 = p0.x + p0.z + p1.x + p1.z;
            float S2 = p0.y + p0.w + p1.y + p1.w;
            float m_ = S1 * (1.f / 256.f);
            mu[r] = m_;
            rs[r] = rsqrtf(fmaf(-m_, m_, S2 * (1.f / 256.f)) + 1e-5f);
        }
        // (no 3rd sync: plane RMW below is same-thread; cross-thread reads
        //  happen after the next gemmA's entry __syncthreads)
#pragma unroll
        for (int nt = 0; nt < 8; ++nt) {
            int col = n0 + nt * 8 + qc * 2;
            float2 gg = *(const float2*)&gam[col];
            float2 ee = *(const float2*)&bet[col];
#pragma unroll
            for (int mt = 0; mt < 2; ++mt)
#pragma unroll
                for (int h = 0; h < 2; ++h) {
                    int r4 = mt * 2 + h;
                    int row = m0 + mt * 16 + h * 8 + qr;
                    float v0 = acc[mt][nt][2 * h], v1 = acc[mt][nt][2 * h + 1];
                    float y0 = fmaxf(fmaf((v0 - mu[r4]) * rs[r4], gg.x, ee.x), 0.f);
                    float y1 = fmaxf(fmaf((v1 - mu[r4]) * rs[r4], gg.y, ee.y), 0.f);
                    u32 off = (u32)row * XA_RS + (u32)col * 2;
                    if (res) {
                        float2 oh = unpbf2(*(u32*)(smc + off));
                        float2 ol = unpbf2(*(u32*)(smc + XA_PL + off));
                        y0 += oh.x + ol.x;
                        y1 += oh.y + ol.y;
                    }
                    u32 hh = packbf2(y0, y1);
                    float2 hf = unpbf2(hh);
                    u32 ll = packbf2(y0 - hf.x, y1 - hf.y);
                    *(u32*)(smc + off)         = hh;
                    *(u32*)(smc + XA_PL + off) = ll;
                }
        }
    };

    // ---- pipeline ----
    gemmA<256>(smb, g_wimg + IMG_STEM, 4, true, acc, tid, lane, m0, nq,
               a_row, a_kh, ph, pe);
    ep256(b_in, g_in, be_in, false);
    for (int b = 0; b < NBLK; ++b) {
        gemmA<256>(smb, g_wimg + IMG_BLK + (size_t)b * IMG_BLKSTR, 16, false,
                   acc, tid, lane, m0, nq, a_row, a_kh, ph, pe);
        ep256(bb + b * HID, gb + b * HID, betab + b * HID, true);
    }
    gemmA<128>(smb, g_wimg + IMG_HEAD, 16, false, acc, tid, lane, m0, nq,
               a_row, a_kh, ph, pe);

    // ---- head epilogue: z = LN(.), write to g_z ----
    {
        const int n0 = nq * 32;
        float s1[4] = {0.f, 0.f, 0.f, 0.f}, s2[4] = {0.f, 0.f, 0.f, 0.f};
#pragma unroll
        for (int nt = 0; nt < 4; ++nt) {
            float2 bp = *(const float2*)&b_out[n0 + nt * 8 + qc * 2];
#pragma unroll
            for (int mt = 0; mt < 2; ++mt) {
                float* c = acc[mt][nt];
                c[0] += bp.x; c[1] += bp.y; c[2] += bp.x; c[3] += bp.y;
                s1[mt*2]   += c[0] + c[1];
                s2[mt*2]    = fmaf(c[0], c[0], fmaf(c[1], c[1], s2[mt*2]));
                s1[mt*2+1] += c[2] + c[3];
                s2[mt*2+1]  = fmaf(c[2], c[2], fmaf(c[3], c[3], s2[mt*2+1]));
            }
        }
#pragma unroll
        for (int r = 0; r < 4; ++r) {
            s1[r] += __shfl_xor_sync(0xffffffffu, s1[r], 1);
            s1[r] += __shfl_xor_sync(0xffffffffu, s1[r], 2);
            s2[r] += __shfl_xor_sync(0xffffffffu, s2[r], 1);
            s2[r] += __shfl_xor_sync(0xffffffffu, s2[r], 2);
        }
        __syncthreads();
        if (qc == 0) {
#pragma unroll
            for (int r = 0; r < 4; ++r) {
                int row = m0 + (r >> 1) * 16 + (r & 1) * 8 + qr;
                part[row * 4 + nq] = make_float2(s1[r], s2[r]);
            }
        }
        __syncthreads();
        float mu[4], rs[4];
#pragma unroll
        for (int r = 0; r < 4; ++r) {
            int row = m0 + (r >> 1) * 16 + (r & 1) * 8 + qr;
            float4 p0 = *(float4*)&part[row * 4];
            float4 p1 = *(float4*)&part[row * 4 + 2];
            float S1 = p0.x + p0.z + p1.x + p1.z;
            float S2 = p0.y + p0.w + p1.y + p1.w;
            float m_ = S1 * (1.f / 128.f);
            mu[r] = m_;
            rs[r] = rsqrtf(fmaf(-m_, m_, S2 * (1.f / 128.f)) + 1e-5f);
        }
        float* zbase = g_z + (size_t)g * (NODES * OUTD);
#pragma unroll
        for (int nt = 0; nt < 4; ++nt) {
            int col = n0 + nt * 8 + qc * 2;
            float2 gg = *(const float2*)&g_out[col];
            float2 ee = *(const float2*)&be_out[col];
#pragma unroll
            for (int mt = 0; mt < 2; ++mt)
#pragma unroll
                for (int h = 0; h < 2; ++h) {
                    int r4 = mt * 2 + h;
                    int row = m0 + mt * 16 + h * 8 + qr;
                    float z0 = fmaf((acc[mt][nt][2*h]   - mu[r4]) * rs[r4], gg.x, ee.x);
                    float z1 = fmaf((acc[mt][nt][2*h+1] - mu[r4]) * rs[r4], gg.y, ee.y);
                    *(float2*)(zbase + (size_t)(mh * 64 + row) * OUTD + col) =
                        make_float2(z0, z1);
                }
        }
    }

    // ---- handoff: second finisher of the graph pair runs the pool ----
    __syncthreads();
    if (tid == 0) {
        __threadfence();                       // publish this CTA's z
        unsigned int old = atomicAdd(&g_cnt[g], 1u);
        s_flag = old;                          // 1 -> we are second
    }
    __syncthreads();
    if (s_flag != 1u) return;
    __threadfence();                           // acquire peer CTA's z

    // ================== fused pool (Gram + softmax + weighted sum) =========
    {
        const int m0p = (w & 3) * 32, nh = w >> 2;
        const int n0p = nh * 64;

        float* sqf   = (float*)(smc + B_SQ);
        float* partf = (float*)(smc + B_PART);
        float* ssm   = (float*)(smc + B_SSM);
        float* wsm   = (float*)(smc + B_WSM);
        float* vpart = (float*)(smc + B_VP);

        // ---- load z, convert to hi/lo planes, row norms ----
        const float* zbase = g_z + (size_t)g * (NODES * OUTD);
#pragma unroll 1
        for (int j = 0; j < 16; ++j) {
            int r = w * 16 + j;
            float4 v = ((const float4*)(zbase + (size_t)r * OUTD))[lane];
            u32 h0 = packbf2(v.x, v.y), h1 = packbf2(v.z, v.w);
            float2 f0 = unpbf2(h0), f1 = unpbf2(h1);
            u32 l0 = packbf2(v.x - f0.x, v.y - f0.y);
            u32 l1 = packbf2(v.z - f1.x, v.w - f1.y);
            u32 off = (u32)r * ZB_RS + (u32)lane * 8;
            *(u32*)(smc + off)             = h0;
            *(u32*)(smc + off + 4)         = h1;
            *(u32*)(smc + ZB_PL + off)     = l0;
            *(u32*)(smc + ZB_PL + off + 4) = l1;
            float sq = fmaf(v.x, v.x, fmaf(v.y, v.y, fmaf(v.z, v.z, v.w * v.w)));
            sq = warpsum(sq);
            if (lane == 0) sqf[r] = sq;
        }
        __syncthreads();

        // ---- Gram via bf16x3 mma (warp tile 32x64) ----
        float acc2[2][8][4];
#pragma unroll
        for (int mt = 0; mt < 2; ++mt)
#pragma unroll
            for (int nt = 0; nt < 8; ++nt)
#pragma unroll
                for (int e = 0; e < 4; ++e) acc2[mt][nt][e] = 0.f;

        const int b_n = (grp >> 1) * 8 + ri, b_kh = grp & 1;
        const u32 azh = smb + (u32)(m0p + a_row) * ZB_RS + a_kh * 16;
        const u32 azl = azh + ZB_PL;
        const u32 bzh = smb + (u32)(n0p + b_n) * ZB_RS + b_kh * 16;
        const u32 bzl = bzh + ZB_PL;
#pragma unroll
        for (int ks = 0; ks < 8; ++ks) {
            const u32 kb = (u32)ks * 32;
            u32 ah0[4], ah1[4], al0[4], al1[4];
            ldsm4(ah0, azh + kb);
            ldsm4(ah1, azh + 16 * ZB_RS + kb);
            ldsm4(al0, azl + kb);
            ldsm4(al1, azl + 16 * ZB_RS + kb);
#pragma unroll
            for (int hf = 0; hf < 2; ++hf) {
                u32 bh[2][4], bl[2][4];
#pragma unroll
                for (int p = 0; p < 2; ++p) {
                    const u32 wa = (u32)(hf * 2 + p) * 16 * ZB_RS + kb;
                    ldsm4(bh[p], bzh + wa);
                    ldsm4(bl[p], bzl + wa);
                }
#pragma unroll
                for (int p = 0; p < 2; ++p)
#pragma unroll
                    for (int h = 0; h < 2; ++h) {
                        int nt = (hf * 2 + p) * 2 + h;
                        mma16816(acc2[0][nt], ah0, bh[p][2*h], bh[p][2*h+1]);
                        mma16816(acc2[1][nt], ah1, bh[p][2*h], bh[p][2*h+1]);
                    }
#pragma unroll
                for (int p = 0; p < 2; ++p)
#pragma unroll
                    for (int h = 0; h < 2; ++h) {
                        int nt = (hf * 2 + p) * 2 + h;
                        mma16816(acc2[0][nt], al0, bh[p][2*h], bh[p][2*h+1]);
                        mma16816(acc2[1][nt], al1, bh[p][2*h], bh[p][2*h+1]);
                    }
#pragma unroll
                for (int p = 0; p < 2; ++p)
#pragma unroll
                    for (int h = 0; h < 2; ++h) {
                        int nt = (hf * 2 + p) * 2 + h;
                        mma16816(acc2[0][nt], ah0, bl[p][2*h], bl[p][2*h+1]);
                        mma16816(acc2[1][nt], ah1, bl[p][2*h], bl[p][2*h+1]);
                    }
            }
        }

        // ---- distances -> per-row sums ----
        float sa[4] = {0.f, 0.f, 0.f, 0.f};
#pragma unroll
        for (int nt = 0; nt < 8; ++nt) {
            int col = n0p + nt * 8 + qc * 2;
            float sc0 = sqf[col], sc1 = sqf[col + 1];
#pragma unroll
            for (int mt = 0; mt < 2; ++mt)
#pragma unroll
                for (int h = 0; h < 2; ++h) {
                    int r4 = mt * 2 + h;
                    int row = m0p + mt * 16 + h * 8 + qr;
                    float sr = sqf[row];
                    float d0 = sr + sc0 - 2.f * acc2[mt][nt][2 * h];
                    float d1 = sr + sc1 - 2.f * acc2[mt][nt][2 * h + 1];
                    float t0 = (col == row) ? 1e-6f
                               : sqrtf(fmaxf(d0, 0.f) + 1e-12f);
                    float t1 = (col + 1 == row) ? 1e-6f
                               : sqrtf(fmaxf(d1, 0.f) + 1e-12f);
                    sa[r4] += t0 + t1;
                }
        }
#pragma unroll
        for (int r = 0; r < 4; ++r) {
            sa[r] += __shfl_xor_sync(0xffffffffu, sa[r], 1);
            sa[r] += __shfl_xor_sync(0xffffffffu, sa[r], 2);
        }
        if (qc == 0) {
#pragma unroll
            for (int r = 0; r < 4; ++r) {
                int row = m0p + (r >> 1) * 16 + (r & 1) * 8 + qr;
                partf[row * 2 + nh] = sa[r];
            }
        }
        __syncthreads();
        if (tid < NODES)
            ssm[tid] = (partf[tid * 2] + partf[tid * 2 + 1]) * (1.f / 128.f);
        __syncthreads();

        // ---- softmax (warp 0) ----
        if (w == 0) {
            const float sc = 1.f / 0.25f;
            float sv[4], mx = -1e30f;
#pragma unroll
            for (int q = 0; q < 4; ++q) {
                sv[q] = ssm[lane + 32 * q] * sc;
                mx = fmaxf(mx, sv[q]);
            }
#pragma unroll
            for (int o = 16; o; o >>= 1)
                mx = fmaxf(mx, __shfl_xor_sync(0xffffffffu, mx, o));
            float e[4], se = 0.f;
#pragma unroll
            for (int q = 0; q < 4; ++q) { e[q] = expf(sv[q] - mx); se += e[q]; }
#pragma unroll
            for (int o = 16; o; o >>= 1)
                se += __shfl_xor_sync(0xffffffffu, se, o);
            float inv = 1.f / se;
#pragma unroll
            for (int q = 0; q < 4; ++q) {
                float ww = e[q] * inv;
                int i = lane + 32 * q;
                wsm[i] = ww;
                out[(size_t)NG * OUTD + (size_t)g * NODES + i] = ww;
            }
        }
        __syncthreads();

        // ---- pool: v[d] = sum_i w_i * (hi+lo)[i][d], 2 i-halves ----
        {
            int d = tid & 127, hseg = tid >> 7;
            float a = 0.f;
#pragma unroll 4
            for (int i = hseg * 64; i < hseg * 64 + 64; ++i) {
                u32 off = (u32)i * ZB_RS + (u32)d * 2;
                float zv = bf2f(*(unsigned short*)(smc + off))
                         + bf2f(*(unsigned short*)(smc + ZB_PL + off));
                a = fmaf(wsm[i], zv, a);
            }
            vpart[hseg * 128 + d] = a;
        }
        __syncthreads();
        if (tid < OUTD)
            out[(size_t)g * OUTD + tid] = vpart[tid] + vpart[128 + tid];
    }
}

}  // namespace lb

extern "C" void kernel_launch(void* const* d_in, const int* in_sizes, int n_in,
                              void* d_out, int out_size)
{
    (void)in_sizes; (void)n_in; (void)out_size;
    const float* H     = (const float*)d_in[0];
    const float* W_in  = (const float*)d_in[2];
    const float* b_in  = (const float*)d_in[3];
    const float* g_in  = (const float*)d_in[4];
    const float* be_in = (const float*)d_in[5];
    const float* Wb    = (const float*)d_in[6];
    const float* bb    = (const float*)d_in[7];
    const float* gb    = (const float*)d_in[8];
    const float* betab = (const float*)d_in[9];
    const float* W_out = (const float*)d_in[10];
    const float* b_out = (const float*)d_in[11];
    const float* g_out = (const float*)d_in[12];
    const float* be_out= (const float*)d_in[13];
    float* out = (float*)d_out;

    lb::prep<<<960, 256>>>(W_in, Wb, W_out);

    cudaFuncSetAttribute(lb::mlp,
                         cudaFuncAttributeMaxDynamicSharedMemorySize,
                         lb::SMEM_A);

    lb::mlp<<<2 * lb::NG, lb::TPA, lb::SMEM_A>>>(
        H, b_in, g_in, be_in, bb, gb, betab, b_out, g_out, be_out, out);
}

// round 16
// speedup vs baseline: 1.0799x; 1.0077x over previous
#include <cuda_runtime.h>
#include <cuda_bf16.h>
#include <cstdint>

// ============================================================================
// LocalBranch round 16: R15 base (512us) + scalar/tail diet:
//  - part-buffer ping-pong -> first __syncthreads of every LN epilogue removed
//  - head epilogue writes own z half directly into pool smem planes (+ sq
//    partials); fused pool only reads the PEER half from g_z (tail halved)
//  mlp: 2048 CTAs x 256 thr, 64 nodes each, bf16x3 mma.sync, tile-packed k16
//  chunks via 2-slot cp.async.bulk ring w/ producer-consumer mbarriers.
// ============================================================================

namespace lb {

using u32 = uint32_t;

constexpr int NODES = 128, IND = 64, HID = 256, OUTD = 128, NBLK = 3, NG = 1024;

// ---- mlp smem ----
constexpr int TPA   = 256;
constexpr int XA_RS = 528;               // x-plane row stride (bytes)
constexpr int XA_PL = 64 * XA_RS;        // 33792 per plane (64 rows)
constexpr int A_RING = 2 * XA_PL;        // 67584
constexpr int A_SLOTB = 16384;           // max chunk bytes (N=256)
constexpr int A_PART = A_RING + 2 * A_SLOTB;   // 100352: 2 x float2[256]
constexpr int A_MB   = A_PART + 4096;    // 104448: 4 mbarriers
constexpr int SMEM_A = A_MB + 48;        // 104496 (x2 = 208992 <= 228KB)

// ---- pool-phase smem overlay (dead x-plane/ring space) ----
constexpr int ZB_RS = 272;               // z-plane row stride (bytes)
constexpr int ZB_PL = 128 * ZB_RS;       // 34816 per plane
constexpr int B_SQ   = 2 * ZB_PL;        // 69632: float[128]
constexpr int B_PART = B_SQ + 512;       // 70144: float[256]
constexpr int B_SSM  = B_PART + 1024;    // float[128]
constexpr int B_WSM  = B_SSM + 512;      // float[128]
constexpr int B_VP   = B_WSM + 512;      // float[256] (ends 73216 < A_PART)

// ---- weight image: k16 chunks of ldsm-ready 128B tiles (see prep) ----
constexpr long IMG_STEM   = 0;                    // 4 chunks x 16384
constexpr long IMG_BLK    = 65536;                // 3 x 16 x 16384
constexpr long IMG_BLKSTR = 262144;
constexpr long IMG_HEAD   = 851968;               // 16 x 8192
__device__ __align__(128) unsigned char g_wimg[983040];
__device__ float g_z[(size_t)NG * NODES * OUTD];  // 64 MB scratch
__device__ unsigned int g_cnt[NG];                // per-graph finish counter

// ---------------- PTX helpers ----------------
__device__ __forceinline__ u32 s2u(const void* p) {
    u32 a;
    asm("{ .reg .u64 t; cvta.to.shared.u64 t, %1; cvt.u32.u64 %0, t; }"
        : "=r"(a) : "l"(p));
    return a;
}
__device__ __forceinline__ void ldsm4(u32* r, u32 addr) {
    asm volatile("ldmatrix.sync.aligned.m8n8.x4.shared.b16 {%0,%1,%2,%3}, [%4];"
                 : "=r"(r[0]), "=r"(r[1]), "=r"(r[2]), "=r"(r[3]) : "r"(addr));
}
__device__ __forceinline__ void mma16816(float* c, const u32* a, u32 b0, u32 b1) {
    asm volatile(
        "mma.sync.aligned.m16n8k16.row.col.f32.bf16.bf16.f32 "
        "{%0,%1,%2,%3}, {%4,%5,%6,%7}, {%8,%9}, {%0,%1,%2,%3};"
        : "+f"(c[0]), "+f"(c[1]), "+f"(c[2]), "+f"(c[3])
        : "r"(a[0]), "r"(a[1]), "r"(a[2]), "r"(a[3]), "r"(b0), "r"(b1));
}
__device__ __forceinline__ void mbar_init(u32 mb, u32 c) {
    asm volatile("mbarrier.init.shared.b64 [%0], %1;" :: "r"(mb), "r"(c)
                 : "memory");
}
__device__ __forceinline__ void mbar_arrive(u32 mb) {
    asm volatile("mbarrier.arrive.shared.b64 _, [%0];" :: "r"(mb) : "memory");
}
__device__ __forceinline__ void mbar_expect_tx(u32 mb, u32 tx) {
    asm volatile("mbarrier.arrive.expect_tx.shared.b64 _, [%0], %1;"
                 :: "r"(mb), "r"(tx) : "memory");
}
__device__ __forceinline__ void bulk_g2s(u32 dst, const void* src, u32 bytes,
                                         u32 mb) {
    asm volatile(
        "cp.async.bulk.shared::cta.global.mbarrier::complete_tx::bytes "
        "[%0], [%1], %2, [%3];"
        :: "r"(dst), "l"(src), "r"(bytes), "r"(mb) : "memory");
}
__device__ __forceinline__ void mbar_wait(u32 mb, u32 parity) {
    asm volatile(
        "{\n\t.reg .pred P;\n\t"
        "W%=:\n\t"
        "mbarrier.try_wait.parity.acquire.cta.shared::cta.b64 P, [%0], %1, 0x989680;\n\t"
        "@!P bra W%=;\n\t}"
        :: "r"(mb), "r"(parity) : "memory");
}

// ---------------- bf16 pack helpers (bf16x2 single-cvt path) ----------------
__device__ __forceinline__ u32 packbf2(float x0, float x1) {
    __nv_bfloat162 t = __floats2bfloat162_rn(x0, x1);
    return *reinterpret_cast<u32*>(&t);
}
__device__ __forceinline__ float2 unpbf2(u32 p) {
    __nv_bfloat162 t = *reinterpret_cast<__nv_bfloat162*>(&p);
    return __bfloat1622float2(t);
}
__device__ __forceinline__ float bf2f(unsigned short v) {
    return __bfloat162float(__ushort_as_bfloat16(v));
}
__device__ __forceinline__ float warpsum(float v) {
#pragma unroll
    for (int o = 16; o; o >>= 1) v += __shfl_xor_sync(0xffffffffu, v, o);
    return v;
}

// ---------------- prep: weights -> split, tile-packed image; zero g_cnt ----
__global__ void prep(const float* __restrict__ Wi, const float* __restrict__ Wb,
                     const float* __restrict__ Wo) {
    int idx = blockIdx.x * 256 + threadIdx.x;        // 245760 total
    if (idx < NG) g_cnt[idx] = 0u;
    const float* W; int k, n, N; long base;
    if (idx < 16384) {
        W = Wi; N = 256; k = idx >> 8; n = idx & 255; base = IMG_STEM;
    } else if (idx < 212992) {
        int e = idx - 16384; int b = e >> 16; e &= 65535;
        W = Wb + (size_t)b * 65536; N = 256; k = e >> 8; n = e & 255;
        base = IMG_BLK + (long)b * IMG_BLKSTR;
    } else {
        int e = idx - 212992;
        W = Wo; N = 128; k = e >> 7; n = e & 127; base = IMG_HEAD;
    }
    float w = W[(size_t)k * N + n];
    __nv_bfloat16 h = __float2bfloat16(w);
    __nv_bfloat16 l = __float2bfloat16(w - __bfloat162float(h));
    int kk = k & 15;
    long off = base + (long)(k >> 4) * ((long)N * 64)
             + (long)(n >> 4) * 512
             + (long)((((n >> 3) & 1) * 2 + (kk >> 3)) * 128)
             + (n & 7) * 16 + (kk & 7) * 2;
    *(__nv_bfloat16*)(g_wimg + off) = h;
    *(__nv_bfloat16*)(g_wimg + off + (long)N * 32) = l;
}

// ---------------- staged GEMM: bulk ring with producer/consumer mbarriers ---
template<int N>   // 256 or 128
__device__ __forceinline__ void gemmA(
    u32 smb, const unsigned char* img, int nchunk, bool first,
    float (&acc)[2][8][4], int tid, int lane, int m0, int nq,
    int a_row, int a_kh, int (&ph)[2], int (&pe)[2])
{
    constexpr int NH = N / 128;            // n16-pair groups per warp (2|1)
    constexpr u32 CB = (u32)N * 64;        // chunk bytes (2 planes)
    const int n16b = nq * (N / 64);        // first n16 index for this warp

    const u32 axh = smb + (u32)(m0 + a_row) * XA_RS + a_kh * 16;
    const u32 axl = axh + XA_PL;
    const u32 fb0 = smb + A_MB,      fb1 = smb + A_MB + 8;
    const u32 eb0 = smb + A_MB + 16, eb1 = smb + A_MB + 24;

#pragma unroll
    for (int mt = 0; mt < 2; ++mt)
#pragma unroll
        for (int nt = 0; nt < 8; ++nt)
#pragma unroll
            for (int e = 0; e < 4; ++e) acc[mt][nt][e] = 0.f;

    __syncthreads();   // plane writes (and, for !first, prior-GEMM arrivals)
    if (tid == 0) {
        if (!first) { mbar_wait(eb0, (u32)pe[0]); pe[0] ^= 1; }
        mbar_expect_tx(fb0, CB);
        bulk_g2s(smb + A_RING, img, CB, fb0);
        if (!first) { mbar_wait(eb1, (u32)pe[1]); pe[1] ^= 1; }
        mbar_expect_tx(fb1, CB);
        bulk_g2s(smb + A_RING + A_SLOTB, img + CB, CB, fb1);
    }

    for (int ch = 0; ch < nchunk; ++ch) {
        const int s = ch & 1;
        const u32 fb = s ? fb1 : fb0;
        const u32 eb = s ? eb1 : eb0;
        mbar_wait(fb, (u32)ph[s]);
        ph[s] ^= 1;
        const u32 slot = smb + A_RING + (u32)s * A_SLOTB;
        const u32 kb = (u32)ch * 32;

        u32 ah0[4], ah1[4], al0[4], al1[4];
        ldsm4(ah0, axh + kb);
        ldsm4(ah1, axh + 16 * XA_RS + kb);
        ldsm4(al0, axl + kb);
        ldsm4(al1, axl + 16 * XA_RS + kb);
#pragma unroll
        for (int hf = 0; hf < NH; ++hf) {
            u32 bh[2][4], bl[2][4];
#pragma unroll
            for (int p = 0; p < 2; ++p) {
                const u32 wa = slot + (u32)(n16b + hf * 2 + p) * 512
                             + (u32)lane * 16;
                ldsm4(bh[p], wa);
                ldsm4(bl[p], wa + (u32)N * 32);
            }
            // term 1: Ahi * Bhi
#pragma unroll
            for (int p = 0; p < 2; ++p)
#pragma unroll
                for (int h = 0; h < 2; ++h) {
                    int nt = (hf * 2 + p) * 2 + h;
                    mma16816(acc[0][nt], ah0, bh[p][2*h], bh[p][2*h+1]);
                    mma16816(acc[1][nt], ah1, bh[p][2*h], bh[p][2*h+1]);
                }
            // term 2: Alo * Bhi
#pragma unroll
            for (int p = 0; p < 2; ++p)
#pragma unroll
                for (int h = 0; h < 2; ++h) {
                    int nt = (hf * 2 + p) * 2 + h;
                    mma16816(acc[0][nt], al0, bh[p][2*h], bh[p][2*h+1]);
                    mma16816(acc[1][nt], al1, bh[p][2*h], bh[p][2*h+1]);
                }
            // term 3: Ahi * Blo
#pragma unroll
            for (int p = 0; p < 2; ++p)
#pragma unroll
                for (int h = 0; h < 2; ++h) {
                    int nt = (hf * 2 + p) * 2 + h;
                    mma16816(acc[0][nt], ah0, bl[p][2*h], bl[p][2*h+1]);
                    mma16816(acc[1][nt], ah1, bl[p][2*h], bl[p][2*h+1]);
                }
        }
        if (lane == 0) mbar_arrive(eb);
        if (ch + 2 < nchunk && tid == 0) {
            mbar_wait(eb, (u32)pe[s]);
            pe[s] ^= 1;
            mbar_expect_tx(fb, CB);
            bulk_g2s(slot, img + (size_t)(ch + 2) * CB, CB, fb);
        }
    }
}

// ---------------- mlp (+ fused pool on second finisher) ----------------
__global__ void __launch_bounds__(TPA, 2)
mlp(const float* __restrict__ H,
    const float* __restrict__ b_in, const float* __restrict__ g_in,
    const float* __restrict__ be_in,
    const float* __restrict__ bb, const float* __restrict__ gb,
    const float* __restrict__ betab,
    const float* __restrict__ b_out, const float* __restrict__ g_out,
    const float* __restrict__ be_out,
    float* __restrict__ out)
{
    extern __shared__ __align__(128) unsigned char smc[];
    __shared__ unsigned int s_flag;
    const u32 smb = s2u(smc);
    const int tid = threadIdx.x, lane = tid & 31, w = tid >> 5;
    const int qr = lane >> 2, qc = lane & 3;
    const int m0 = (w & 1) * 32, nq = w >> 1;
    const int grp = lane >> 3, ri = lane & 7;
    const int a_row = (grp & 1) * 8 + ri, a_kh = grp >> 1;
    const int g = blockIdx.x >> 1, mh = blockIdx.x & 1;

    int ph[2] = {0, 0};   // full-barrier phases
    int pe[2] = {0, 0};   // empty-barrier phases

    if (tid == 0) {
        mbar_init(smb + A_MB, 1);        // fb0
        mbar_init(smb + A_MB + 8, 1);    // fb1
        mbar_init(smb + A_MB + 16, 8);   // eb0
        mbar_init(smb + A_MB + 24, 8);   // eb1
    }

    // ---- load H (64 rows, node base mh*64) -> hi/lo planes ----
    {
        const int row = tid >> 2, c4 = tid & 3;
        const float4* hs = (const float4*)(H + (size_t)g * NODES * IND
                                           + (size_t)(mh * 64 + row) * IND
                                           + c4 * 16);
        const u32 off = (u32)row * XA_RS + (u32)c4 * 32;
#pragma unroll
        for (int q = 0; q < 4; ++q) {
            float4 v = hs[q];
            u32 h0 = packbf2(v.x, v.y), h1 = packbf2(v.z, v.w);
            float2 f0 = unpbf2(h0), f1 = unpbf2(h1);
            u32 l0 = packbf2(v.x - f0.x, v.y - f0.y);
            u32 l1 = packbf2(v.z - f1.x, v.w - f1.y);
            *(u32*)(smc + off + q * 8)             = h0;
            *(u32*)(smc + off + q * 8 + 4)         = h1;
            *(u32*)(smc + XA_PL + off + q * 8)     = l0;
            *(u32*)(smc + XA_PL + off + q * 8 + 4) = l1;
        }
    }

    float acc[2][8][4];

    // ---- LN(+relu,+residual) epilogue N=256; part ping-pong (pp) ----
    auto ep256 = [&](const float* bias, const float* gam, const float* bet,
                     bool res, int pp) {
        float2* part = (float2*)(smc + A_PART + pp * 2048);
        const int n0 = nq * 64;
        float s1[4] = {0.f, 0.f, 0.f, 0.f}, s2[4] = {0.f, 0.f, 0.f, 0.f};
#pragma unroll
        for (int nt = 0; nt < 8; ++nt) {
            float2 bp = *(const float2*)&bias[n0 + nt * 8 + qc * 2];
#pragma unroll
            for (int mt = 0; mt < 2; ++mt) {
                float* c = acc[mt][nt];
                c[0] += bp.x; c[1] += bp.y; c[2] += bp.x; c[3] += bp.y;
                s1[mt*2]   += c[0] + c[1];
                s2[mt*2]    = fmaf(c[0], c[0], fmaf(c[1], c[1], s2[mt*2]));
                s1[mt*2+1] += c[2] + c[3];
                s2[mt*2+1]  = fmaf(c[2], c[2], fmaf(c[3], c[3], s2[mt*2+1]));
            }
        }
#pragma unroll
        for (int r = 0; r < 4; ++r) {
            s1[r] += __shfl_xor_sync(0xffffffffu, s1[r], 1);
            s1[r] += __shfl_xor_sync(0xffffffffu, s1[r], 2);
            s2[r] += __shfl_xor_sync(0xffffffffu, s2[r], 1);
            s2[r] += __shfl_xor_sync(0xffffffffu, s2[r], 2);
        }
        // no pre-sync: part buffer is ping-ponged (last user 2 epilogues ago)
        if (qc == 0) {
#pragma unroll
            for (int r = 0; r < 4; ++r) {
                int row = m0 + (r >> 1) * 16 + (r & 1) * 8 + qr;
                part[row * 4 + nq] = make_float2(s1[r], s2[r]);
            }
        }
        __syncthreads();   // stats visible; also drains all warps from GEMM
        float mu[4], rs[4];
#pragma unroll
        for (int r = 0; r < 4; ++r) {
            int row = m0 + (r >> 1) * 16 + (r & 1) * 8 + qr;
            float4 p0 = *(float4*)&part[row * 4];
            float4 p1 = *(float4*)&part[row * 4 + 2];
            float S1 = p0.x + p0.z + p1.x + p1.z;
            float S2 = p0.y + p0.w + p1.y + p1.w;
            float m_ = S1 * (1.f / 256.f);
            mu[r] = m_;
            rs[r] = rsqrtf(fmaf(-m_, m_, S2 * (1.f / 256.f)) + 1e-5f);
        }
#pragma unroll
        for (int nt = 0; nt < 8; ++nt) {
            int col = n0 + nt * 8 + qc * 2;
            float2 gg = *(const float2*)&gam[col];
            float2 ee = *(const float2*)&bet[col];
#pragma unroll
            for (int mt = 0; mt < 2; ++mt)
#pragma unroll
                for (int h = 0; h < 2; ++h) {
                    int r4 = mt * 2 + h;
                    int row = m0 + mt * 16 + h * 8 + qr;
                    float v0 = acc[mt][nt][2 * h], v1 = acc[mt][nt][2 * h + 1];
                    float y0 = fmaxf(fmaf((v0 - mu[r4]) * rs[r4], gg.x, ee.x), 0.f);
                    float y1 = fmaxf(fmaf((v1 - mu[r4]) * rs[r4], gg.y, ee.y), 0.f);
                    u32 off = (u32)row * XA_RS + (u32)col * 2;
                    if (res) {
                        float2 oh = unpbf2(*(u32*)(smc + off));
                        float2 ol = unpbf2(*(u32*)(smc + XA_PL + off));
                        y0 += oh.x + ol.x;
                        y1 += oh.y + ol.y;
                    }
                    u32 hh = packbf2(y0, y1);
                    float2 hf = unpbf2(hh);
                    u32 ll = packbf2(y0 - hf.x, y1 - hf.y);
                    *(u32*)(smc + off)         = hh;
                    *(u32*)(smc + XA_PL + off) = ll;
                }
        }
    };

    // ---- pipeline ----
    gemmA<256>(smb, g_wimg + IMG_STEM, 4, true, acc, tid, lane, m0, nq,
               a_row, a_kh, ph, pe);
    ep256(b_in, g_in, be_in, false, 0);
    for (int b = 0; b < NBLK; ++b) {
        gemmA<256>(smb, g_wimg + IMG_BLK + (size_t)b * IMG_BLKSTR, 16, false,
                   acc, tid, lane, m0, nq, a_row, a_kh, ph, pe);
        ep256(bb + b * HID, gb + b * HID, betab + b * HID, true, (b + 1) & 1);
    }
    gemmA<128>(smb, g_wimg + IMG_HEAD, 16, false, acc, tid, lane, m0, nq,
               a_row, a_kh, ph, pe);

    // ---- head epilogue: z = LN(.); write g_z + OWN pool planes + sq parts --
    {
        float2* part = (float2*)(smc + A_PART);          // pp=0 (last was 1)
        float* partf = (float*)(smc + B_PART);           // sq partials (dead ring)
        const int n0 = nq * 32;
        float s1[4] = {0.f, 0.f, 0.f, 0.f}, s2[4] = {0.f, 0.f, 0.f, 0.f};
#pragma unroll
        for (int nt = 0; nt < 4; ++nt) {
            float2 bp = *(const float2*)&b_out[n0 + nt * 8 + qc * 2];
#pragma unroll
            for (int mt = 0; mt < 2; ++mt) {
                float* c = acc[mt][nt];
                c[0] += bp.x; c[1] += bp.y; c[2] += bp.x; c[3] += bp.y;
                s1[mt*2]   += c[0] + c[1];
                s2[mt*2]    = fmaf(c[0], c[0], fmaf(c[1], c[1], s2[mt*2]));
                s1[mt*2+1] += c[2] + c[3];
                s2[mt*2+1]  = fmaf(c[2], c[2], fmaf(c[3], c[3], s2[mt*2+1]));
            }
        }
#pragma unroll
        for (int r = 0; r < 4; ++r) {
            s1[r] += __shfl_xor_sync(0xffffffffu, s1[r], 1);
            s1[r] += __shfl_xor_sync(0xffffffffu, s1[r], 2);
            s2[r] += __shfl_xor_sync(0xffffffffu, s2[r], 1);
            s2[r] += __shfl_xor_sync(0xffffffffu, s2[r], 2);
        }
        if (qc == 0) {
#pragma unroll
            for (int r = 0; r < 4; ++r) {
                int row = m0 + (r >> 1) * 16 + (r & 1) * 8 + qr;
                part[row * 4 + nq] = make_float2(s1[r], s2[r]);
            }
        }
        __syncthreads();   // stats visible; drains all warps from head GEMM
        float mu[4], rs[4];
#pragma unroll
        for (int r = 0; r < 4; ++r) {
            int row = m0 + (r >> 1) * 16 + (r & 1) * 8 + qr;
            float4 p0 = *(float4*)&part[row * 4];
            float4 p1 = *(float4*)&part[row * 4 + 2];
            float S1 = p0.x + p0.z + p1.x + p1.z;
            float S2 = p0.y + p0.w + p1.y + p1.w;
            float m_ = S1 * (1.f / 128.f);
            mu[r] = m_;
            rs[r] = rsqrtf(fmaf(-m_, m_, S2 * (1.f / 128.f)) + 1e-5f);
        }
        float* zbase = g_z + (size_t)g * (NODES * OUTD);
        float sqp[4] = {0.f, 0.f, 0.f, 0.f};
#pragma unroll
        for (int nt = 0; nt < 4; ++nt) {
            int col = n0 + nt * 8 + qc * 2;
            float2 gg = *(const float2*)&g_out[col];
            float2 ee = *(const float2*)&be_out[col];
#pragma unroll
            for (int mt = 0; mt < 2; ++mt)
#pragma unroll
                for (int h = 0; h < 2; ++h) {
                    int r4 = mt * 2 + h;
                    int row = m0 + mt * 16 + h * 8 + qr;
                    int grow = mh * 64 + row;
                    float z0 = fmaf((acc[mt][nt][2*h]   - mu[r4]) * rs[r4], gg.x, ee.x);
                    float z1 = fmaf((acc[mt][nt][2*h+1] - mu[r4]) * rs[r4], gg.y, ee.y);
                    *(float2*)(zbase + (size_t)grow * OUTD + col) =
                        make_float2(z0, z1);
                    // own pool planes (x planes + ring are dead now)
                    u32 zoff = (u32)grow * ZB_RS + (u32)col * 2;
                    u32 hh = packbf2(z0, z1);
                    float2 hf = unpbf2(hh);
                    *(u32*)(smc + zoff)         = hh;
                    *(u32*)(smc + ZB_PL + zoff) = packbf2(z0 - hf.x, z1 - hf.y);
                    sqp[r4] = fmaf(z0, z0, fmaf(z1, z1, sqp[r4]));
                }
        }
#pragma unroll
        for (int r = 0; r < 4; ++r) {
            sqp[r] += __shfl_xor_sync(0xffffffffu, sqp[r], 1);
            sqp[r] += __shfl_xor_sync(0xffffffffu, sqp[r], 2);
        }
        if (qc == 0) {
#pragma unroll
            for (int r = 0; r < 4; ++r) {
                int row = m0 + (r >> 1) * 16 + (r & 1) * 8 + qr;
                partf[row * 4 + nq] = sqp[r];
            }
        }
    }

    // ---- handoff: second finisher of the graph pair runs the pool ----
    __syncthreads();
    if (tid == 0) {
        __threadfence();                       // publish this CTA's z
        unsigned int old = atomicAdd(&g_cnt[g], 1u);
        s_flag = old;                          // 1 -> we are second
    }
    __syncthreads();
    if (s_flag != 1u) return;
    __threadfence();                           // acquire peer CTA's z

    // ================== fused pool (Gram + softmax + weighted sum) =========
    {
        const int m0p = (w & 3) * 32, nh = w >> 2;
        const int n0p = nh * 64;
        const int peer = (mh ^ 1) * 64;

        float* sqf   = (float*)(smc + B_SQ);
        float* partf = (float*)(smc + B_PART);
        float* ssm   = (float*)(smc + B_SSM);
        float* wsm   = (float*)(smc + B_WSM);
        float* vpart = (float*)(smc + B_VP);

        // ---- own sq from head-epilogue partials ----
        if (tid < 64)
            sqf[mh * 64 + tid] = partf[tid * 4] + partf[tid * 4 + 1]
                               + partf[tid * 4 + 2] + partf[tid * 4 + 3];

        // ---- load PEER half from g_z, convert to planes, row norms ----
        const float* zbase = g_z + (size_t)g * (NODES * OUTD);
#pragma unroll 1
        for (int j = 0; j < 8; ++j) {
            int r = peer + w * 8 + j;
            float4 v = ((const float4*)(zbase + (size_t)r * OUTD))[lane];
            u32 h0 = packbf2(v.x, v.y), h1 = packbf2(v.z, v.w);
            float2 f0 = unpbf2(h0), f1 = unpbf2(h1);
            u32 l0 = packbf2(v.x - f0.x, v.y - f0.y);
            u32 l1 = packbf2(v.z - f1.x, v.w - f1.y);
            u32 off = (u32)r * ZB_RS + (u32)lane * 8;
            *(u32*)(smc + off)             = h0;
            *(u32*)(smc + off + 4)         = h1;
            *(u32*)(smc + ZB_PL + off)     = l0;
            *(u32*)(smc + ZB_PL + off + 4) = l1;
            float sq = fmaf(v.x, v.x, fmaf(v.y, v.y, fmaf(v.z, v.z, v.w * v.w)));
            sq = warpsum(sq);
            if (lane == 0) sqf[r] = sq;
        }
        __syncthreads();

        // ---- Gram via bf16x3 mma (warp tile 32x64) ----
        float acc2[2][8][4];
#pragma unroll
        for (int mt = 0; mt < 2; ++mt)
#pragma unroll
            for (int nt = 0; nt < 8; ++nt)
#pragma unroll
                for (int e = 0; e < 4; ++e) acc2[mt][nt][e] = 0.f;

        const int b_n = (grp >> 1) * 8 + ri, b_kh = grp & 1;
        const u32 azh = smb + (u32)(m0p + a_row) * ZB_RS + a_kh * 16;
        const u32 azl = azh + ZB_PL;
        const u32 bzh = smb + (u32)(n0p + b_n) * ZB_RS + b_kh * 16;
        const u32 bzl = bzh + ZB_PL;
#pragma unroll
        for (int ks = 0; ks < 8; ++ks) {
            const u32 kb = (u32)ks * 32;
            u32 ah0[4], ah1[4], al0[4], al1[4];
            ldsm4(ah0, azh + kb);
            ldsm4(ah1, azh + 16 * ZB_RS + kb);
            ldsm4(al0, azl + kb);
            ldsm4(al1, azl + 16 * ZB_RS + kb);
#pragma unroll
            for (int hf = 0; hf < 2; ++hf) {
                u32 bh[2][4], bl[2][4];
#pragma unroll
                for (int p = 0; p < 2; ++p) {
                    const u32 wa = (u32)(hf * 2 + p) * 16 * ZB_RS + kb;
                    ldsm4(bh[p], bzh + wa);
                    ldsm4(bl[p], bzl + wa);
                }
#pragma unroll
                for (int p = 0; p < 2; ++p)
#pragma unroll
                    for (int h = 0; h < 2; ++h) {
                        int nt = (hf * 2 + p) * 2 + h;
                        mma16816(acc2[0][nt], ah0, bh[p][2*h], bh[p][2*h+1]);
                        mma16816(acc2[1][nt], ah1, bh[p][2*h], bh[p][2*h+1]);
                    }
#pragma unroll
                for (int p = 0; p < 2; ++p)
#pragma unroll
                    for (int h = 0; h < 2; ++h) {
                        int nt = (hf * 2 + p) * 2 + h;
                        mma16816(acc2[0][nt], al0, bh[p][2*h], bh[p][2*h+1]);
                        mma16816(acc2[1][nt], al1, bh[p][2*h], bh[p][2*h+1]);
                    }
#pragma unroll
                for (int p = 0; p < 2; ++p)
#pragma unroll
                    for (int h = 0; h < 2; ++h) {
                        int nt = (hf * 2 + p) * 2 + h;
                        mma16816(acc2[0][nt], ah0, bl[p][2*h], bl[p][2*h+1]);
                        mma16816(acc2[1][nt], ah1, bl[p][2*h], bl[p][2*h+1]);
                    }
            }
        }

        // ---- distances -> per-row sums ----
        float sa[4] = {0.f, 0.f, 0.f, 0.f};
#pragma unroll
        for (int nt = 0; nt < 8; ++nt) {
            int col = n0p + nt * 8 + qc * 2;
            float sc0 = sqf[col], sc1 = sqf[col + 1];
#pragma unroll
            for (int mt = 0; mt < 2; ++mt)
#pragma unroll
                for (int h = 0; h < 2; ++h) {
                    int r4 = mt * 2 + h;
                    int row = m0p + mt * 16 + h * 8 + qr;
                    float sr = sqf[row];
                    float d0 = sr + sc0 - 2.f * acc2[mt][nt][2 * h];
                    float d1 = sr + sc1 - 2.f * acc2[mt][nt][2 * h + 1];
                    float t0 = (col == row) ? 1e-6f
                               : sqrtf(fmaxf(d0, 0.f) + 1e-12f);
                    float t1 = (col + 1 == row) ? 1e-6f
                               : sqrtf(fmaxf(d1, 0.f) + 1e-12f);
                    sa[r4] += t0 + t1;
                }
        }
#pragma unroll
        for (int r = 0; r < 4; ++r) {
            sa[r] += __shfl_xor_sync(0xffffffffu, sa[r], 1);
            sa[r] += __shfl_xor_sync(0xffffffffu, sa[r], 2);
        }
        if (qc == 0) {
#pragma unroll
            for (int r = 0; r < 4; ++r) {
                int row = m0p + (r >> 1) * 16 + (r & 1) * 8 + qr;
                partf[row * 2 + nh] = sa[r];
            }
        }
        __syncthreads();
        if (tid < NODES)
            ssm[tid] = (partf[tid * 2] + partf[tid * 2 + 1]) * (1.f / 128.f);
        __syncthreads();

        // ---- softmax (warp 0) ----
        if (w == 0) {
            const float sc = 1.f / 0.25f;
            float sv[4], mx = -1e30f;
#pragma unroll
            for (int q = 0; q < 4; ++q) {
                sv[q] = ssm[lane + 32 * q] * sc;
                mx = fmaxf(mx, sv[q]);
            }
#pragma unroll
            for (int o = 16; o; o >>= 1)
                mx = fmaxf(mx, __shfl_xor_sync(0xffffffffu, mx, o));
            float e[4], se = 0.f;
#pragma unroll
            for (int q = 0; q < 4; ++q) { e[q] = expf(sv[q] - mx); se += e[q]; }
#pragma unroll
            for (int o = 16; o; o >>= 1)
                se += __shfl_xor_sync(0xffffffffu, se, o);
            float inv = 1.f / se;
#pragma unroll
            for (int q = 0; q < 4; ++q) {
                float ww = e[q] * inv;
                int i = lane + 32 * q;
                wsm[i] = ww;
                out[(size_t)NG * OUTD + (size_t)g * NODES + i] = ww;
            }
        }
        __syncthreads();

        // ---- pool: v[d] = sum_i w_i * (hi+lo)[i][d], 2 i-halves ----
        {
            int d = tid & 127, hseg = tid >> 7;
            float a = 0.f;
#pragma unroll 4
            for (int i = hseg * 64; i < hseg * 64 + 64; ++i) {
                u32 off = (u32)i * ZB_RS + (u32)d * 2;
                float zv = bf2f(*(unsigned short*)(smc + off))
                         + bf2f(*(unsigned short*)(smc + ZB_PL + off));
                a = fmaf(wsm[i], zv, a);
            }
            vpart[hseg * 128 + d] = a;
        }
        __syncthreads();
        if (tid < OUTD)
            out[(size_t)g * OUTD + tid] = vpart[tid] + vpart[128 + tid];
    }
}

}  // namespace lb

extern "C" void kernel_launch(void* const* d_in, const int* in_sizes, int n_in,
                              void* d_out, int out_size)
{
    (void)in_sizes; (void)n_in; (void)out_size;
    const float* H     = (const float*)d_in[0];
    const float* W_in  = (const float*)d_in[2];
    const float* b_in  = (const float*)d_in[3];
    const float* g_in  = (const float*)d_in[4];
    const float* be_in = (const float*)d_in[5];
    const float* Wb    = (const float*)d_in[6];
    const float* bb    = (const float*)d_in[7];
    const float* gb    = (const float*)d_in[8];
    const float* betab = (const float*)d_in[9];
    const float* W_out = (const float*)d_in[10];
    const float* b_out = (const float*)d_in[11];
    const float* g_out = (const float*)d_in[12];
    const float* be_out= (const float*)d_in[13];
    float* out = (float*)d_out;

    lb::prep<<<960, 256>>>(W_in, Wb, W_out);

    cudaFuncSetAttribute(lb::mlp,
                         cudaFuncAttributeMaxDynamicSharedMemorySize,
                         lb::SMEM_A);

    lb::mlp<<<2 * lb::NG, lb::TPA, lb::SMEM_A>>>(
        H, b_in, g_in, be_in, bb, gb, betab, b_out, g_out, be_out, out);
}